// round 1
// baseline (speedup 1.0000x reference)
#include <cuda_runtime.h>
#include <cuda_bf16.h>
#include <cstdint>

#define TE      64
#define THREADS 256
#define MCOLS   256     // padded column count (real = 224)
#define RCOLS   224

// Precomputed fused weight M[64][256] (includes diag(s), proj, and 0.25 scale)
// and bias row c[256] (includes rad_b2 contribution).
__device__ __align__(16) float g_M[64 * MCOLS];
__device__ __align__(16) float g_c[MCOLS];

// ---------------------------------------------------------------------------
// Precompute: M[k][col] = 0.25 * sum_c rad_w2[k][woff+c] * s[c] * P[c][col']
// row k==64 is the bias row (uses rad_b2 instead of rad_w2 row).
// ---------------------------------------------------------------------------
__global__ void precompute_kernel(const float* __restrict__ exp_w,
                                  const float* __restrict__ exp_b,
                                  const float* __restrict__ rad_w2,
                                  const float* __restrict__ rad_b2,
                                  const float* __restrict__ pw0,
                                  const float* __restrict__ pw1,
                                  const float* __restrict__ pw2) {
    int k   = blockIdx.x;    // 0..64 (64 = bias row)
    int col = threadIdx.x;   // 0..255
    float acc = 0.f;
    if (col < RCOLS) {
        const float* P;
        int d, woff, pstride;
        if (col < 128)      { P = pw0; d = col;       woff = 0;   pstride = 128; }
        else if (col < 192) { P = pw1; d = col - 128; woff = 128; pstride = 64;  }
        else                { P = pw2; d = col - 192; woff = 256; pstride = 32;  }
        for (int c = 0; c < 128; c++) {
            float w = (k < 64) ? rad_w2[k * 384 + woff + c] : rad_b2[woff + c];
            float s = exp_w[c] + exp_b[c];
            acc += w * s * P[c * pstride + d];
        }
        acc *= 0.25f;   // 1/sqrt(AVG_AGG)
    }
    if (k < 64) g_M[k * MCOLS + col] = acc;
    else        g_c[col] = acc;
}

// vectorized global reduction (sm_90+): 4 floats, 16B-aligned address
__device__ __forceinline__ void red4(float* p, float a, float b, float c, float d) {
    asm volatile("red.global.add.v4.f32 [%0], {%1, %2, %3, %4};"
                 :: "l"(p), "f"(a), "f"(b), "f"(c), "f"(d) : "memory");
}

// ---------------------------------------------------------------------------
// Main fused kernel: 1 CTA = 64 edges, 256 threads.
// Stage A: h = X @ W1 + b1 ; LN(gamma,beta) ; silu  -> g (64x64 tile)
// Stage B: t = g @ M + c                             (64x224 tile)
// Stage C: expand t via sh outer products -> red.v4 scatter into out[dst]
// ---------------------------------------------------------------------------
__global__ __launch_bounds__(THREADS, 2)
void edge_main_kernel(const float* __restrict__ edge_attr,
                      const float* __restrict__ edge_scalars,
                      const int*   __restrict__ edge_dst,
                      const float* __restrict__ rad_w1,
                      const float* __restrict__ rad_b1,
                      const float* __restrict__ rad_gamma,
                      const float* __restrict__ rad_beta,
                      const float* __restrict__ proj_b0,
                      float* __restrict__ out,
                      int E)
{
    extern __shared__ float smem[];
    float* Ms   = smem;                   // 64*256
    float* XG   = Ms + 64 * MCOLS;        // 64*68  (Xt, later reused as Gt)
    float* W1s  = XG + 64 * 68;           // 64*68
    float* shS  = W1s + 64 * 68;          // 64*10
    int*   dstS = (int*)(shS + 64 * 10);  // 64
    float* b1s  = (float*)(dstS + 64);    // 64
    float* gms  = b1s + 64;               // 64
    float* bts  = gms + 64;               // 64
    float* cS   = bts + 64;               // 256
    float* b0s  = cS + MCOLS;             // 128

    const int tid = threadIdx.x;
    const int e0  = blockIdx.x * TE;

    // ---------------- load phase ----------------
    {
        const float4* src = (const float4*)g_M;
        float4* dst4 = (float4*)Ms;
        #pragma unroll
        for (int i = 0; i < (64 * MCOLS / 4) / THREADS; i++)
            dst4[tid + i * THREADS] = src[tid + i * THREADS];
    }
    for (int i = tid; i < 64 * 64; i += THREADS) {
        int k = i >> 6, j = i & 63;
        W1s[k * 68 + j] = rad_w1[i];
    }
    for (int i = tid; i < TE * 64; i += THREADS) {
        int e = i >> 6, k = i & 63;
        int ge = e0 + e;
        XG[k * 68 + e] = (ge < E) ? edge_scalars[(size_t)ge * 64 + k] : 0.f;
    }
    for (int i = tid; i < TE * 9; i += THREADS) {
        int e = i / 9, m = i % 9;
        int ge = e0 + e;
        shS[e * 10 + m] = (ge < E) ? edge_attr[(size_t)ge * 9 + m] : 0.f;
    }
    if (tid < TE) {
        int ge = e0 + tid;
        dstS[tid] = (ge < E) ? edge_dst[ge] : 0;
    }
    if (tid < 64) { b1s[tid] = rad_b1[tid]; gms[tid] = rad_gamma[tid]; bts[tid] = rad_beta[tid]; }
    for (int i = tid; i < MCOLS; i += THREADS) cS[i] = g_c[i];
    if (tid < 128) b0s[tid] = proj_b0[tid] * 0.25f;
    __syncthreads();

    // ---------------- stage A: 64x64x64 GEMM + LN + silu ----------------
    {
        const int fg = tid & 15;   // feature group (4 feats)
        const int eg = tid >> 4;   // edge group (4 edges)
        float acc[4][4];
        #pragma unroll
        for (int i = 0; i < 4; i++)
            #pragma unroll
            for (int j = 0; j < 4; j++) acc[i][j] = 0.f;

        #pragma unroll 4
        for (int k = 0; k < 64; k++) {
            float4 xv = *(const float4*)&XG[k * 68 + eg * 4];
            float4 wv = *(const float4*)&W1s[k * 68 + fg * 4];
            float xs[4] = {xv.x, xv.y, xv.z, xv.w};
            float ws[4] = {wv.x, wv.y, wv.z, wv.w};
            #pragma unroll
            for (int i = 0; i < 4; i++)
                #pragma unroll
                for (int j = 0; j < 4; j++)
                    acc[i][j] += xs[i] * ws[j];
        }

        float h[4][4], mean[4], rstd[4];
        #pragma unroll
        for (int i = 0; i < 4; i++) {
            float ps = 0.f, pq = 0.f;
            #pragma unroll
            for (int j = 0; j < 4; j++) {
                float v = acc[i][j] + b1s[fg * 4 + j];
                h[i][j] = v;
                ps += v; pq += v * v;
            }
            #pragma unroll
            for (int o = 8; o >= 1; o >>= 1) {
                ps += __shfl_xor_sync(0xffffffffu, ps, o, 16);
                pq += __shfl_xor_sync(0xffffffffu, pq, o, 16);
            }
            float mu  = ps * (1.f / 64.f);
            float var = pq * (1.f / 64.f) - mu * mu;
            mean[i] = mu;
            rstd[i] = rsqrtf(var + 1e-5f);
        }

        __syncthreads();   // all Xt reads done before overwriting XG with Gt
        #pragma unroll
        for (int i = 0; i < 4; i++) {
            #pragma unroll
            for (int j = 0; j < 4; j++) {
                int jj = fg * 4 + j;
                float v = (h[i][j] - mean[i]) * rstd[i] * gms[jj] + bts[jj];
                v = v / (1.f + __expf(-v));          // silu
                XG[jj * 68 + (eg * 4 + i)] = v;      // Gt[k][e]
            }
        }
    }
    __syncthreads();

    // ---------------- stage B: 64x256x64 GEMM ----------------
    const int cg  = tid & 31;   // 8 columns
    const int eg2 = tid >> 5;   // 8 edges
    float t[8][8];
    #pragma unroll
    for (int i = 0; i < 8; i++)
        #pragma unroll
        for (int j = 0; j < 8; j++) t[i][j] = 0.f;

    #pragma unroll 2
    for (int k = 0; k < 64; k++) {
        float4 ga = *(const float4*)&XG[k * 68 + eg2 * 8];
        float4 gb = *(const float4*)&XG[k * 68 + eg2 * 8 + 4];
        float4 m0 = *(const float4*)&Ms[k * MCOLS + cg * 8];
        float4 m1 = *(const float4*)&Ms[k * MCOLS + cg * 8 + 4];
        float gv[8] = {ga.x, ga.y, ga.z, ga.w, gb.x, gb.y, gb.z, gb.w};
        float mv[8] = {m0.x, m0.y, m0.z, m0.w, m1.x, m1.y, m1.z, m1.w};
        #pragma unroll
        for (int i = 0; i < 8; i++)
            #pragma unroll
            for (int j = 0; j < 8; j++)
                t[i][j] += gv[i] * mv[j];
    }
    {
        float cj[8];
        #pragma unroll
        for (int j = 0; j < 8; j++) cj[j] = cS[cg * 8 + j];
        #pragma unroll
        for (int i = 0; i < 8; i++)
            #pragma unroll
            for (int j = 0; j < 8; j++) t[i][j] += cj[j];
    }

    // ---------------- stage C: expand + vector atomic scatter ----------------
    const int colbase = cg * 8;
    if (colbase < 128) {
        // region 0: y0 = sh0 * t0 + 0.25*proj_b0
        float b0v[8];
        #pragma unroll
        for (int j = 0; j < 8; j++) b0v[j] = b0s[colbase + j];
        #pragma unroll
        for (int i = 0; i < 8; i++) {
            int e = eg2 * 8 + i;
            if (e0 + e >= E) continue;
            float s0 = shS[e * 10 + 0];
            float* base = out + (size_t)dstS[e] * 480 + colbase;
            red4(base,     fmaf(s0, t[i][0], b0v[0]), fmaf(s0, t[i][1], b0v[1]),
                           fmaf(s0, t[i][2], b0v[2]), fmaf(s0, t[i][3], b0v[3]));
            red4(base + 4, fmaf(s0, t[i][4], b0v[4]), fmaf(s0, t[i][5], b0v[5]),
                           fmaf(s0, t[i][6], b0v[6]), fmaf(s0, t[i][7], b0v[7]));
        }
    } else if (colbase < 192) {
        // region 1: y1[128 + d*3 + m] = t1[d] * sh1[m], 8 d's -> 24 consecutive floats
        const int off = 128 + (colbase - 128) * 3;
        #pragma unroll
        for (int i = 0; i < 8; i++) {
            int e = eg2 * 8 + i;
            if (e0 + e >= E) continue;
            float s1[3] = {shS[e * 10 + 1], shS[e * 10 + 2], shS[e * 10 + 3]};
            float* base = out + (size_t)dstS[e] * 480 + off;
            #pragma unroll
            for (int g = 0; g < 6; g++) {
                const int p = g * 4;
                red4(base + p,
                     t[i][(p + 0) / 3] * s1[(p + 0) % 3],
                     t[i][(p + 1) / 3] * s1[(p + 1) % 3],
                     t[i][(p + 2) / 3] * s1[(p + 2) % 3],
                     t[i][(p + 3) / 3] * s1[(p + 3) % 3]);
            }
        }
    } else if (colbase < RCOLS) {
        // region 2: y2[320 + d*5 + m] = t2[d] * sh2[m], 8 d's -> 40 consecutive floats
        const int off = 320 + (colbase - 192) * 5;
        #pragma unroll
        for (int i = 0; i < 8; i++) {
            int e = eg2 * 8 + i;
            if (e0 + e >= E) continue;
            float s2[5] = {shS[e * 10 + 4], shS[e * 10 + 5], shS[e * 10 + 6],
                           shS[e * 10 + 7], shS[e * 10 + 8]};
            float* base = out + (size_t)dstS[e] * 480 + off;
            #pragma unroll
            for (int g = 0; g < 10; g++) {
                const int p = g * 4;
                red4(base + p,
                     t[i][(p + 0) / 5] * s2[(p + 0) % 5],
                     t[i][(p + 1) / 5] * s2[(p + 1) % 5],
                     t[i][(p + 2) / 5] * s2[(p + 2) % 5],
                     t[i][(p + 3) / 5] * s2[(p + 3) % 5]);
            }
        }
    }
    // colbase >= 224: padding columns, nothing to emit
}

// ---------------------------------------------------------------------------
extern "C" void kernel_launch(void* const* d_in, const int* in_sizes, int n_in,
                              void* d_out, int out_size) {
    const float* edge_attr    = (const float*)d_in[1];
    const float* edge_scalars = (const float*)d_in[2];
    const int*   edge_dst     = (const int*)d_in[4];
    const float* exp_w   = (const float*)d_in[6];
    const float* exp_b   = (const float*)d_in[7];
    const float* rad_w1  = (const float*)d_in[8];
    const float* rad_b1  = (const float*)d_in[9];
    const float* rad_gamma = (const float*)d_in[10];
    const float* rad_beta  = (const float*)d_in[11];
    const float* rad_w2  = (const float*)d_in[12];
    const float* rad_b2  = (const float*)d_in[13];
    const float* proj_w0 = (const float*)d_in[14];
    const float* proj_b0 = (const float*)d_in[15];
    const float* proj_w1 = (const float*)d_in[16];
    const float* proj_w2 = (const float*)d_in[17];
    float* out = (float*)d_out;
    const int E = in_sizes[4];

    // output is poisoned; atomics need zeros
    cudaMemsetAsync(d_out, 0, (size_t)out_size * sizeof(float));

    precompute_kernel<<<65, 256>>>(exp_w, exp_b, rad_w2, rad_b2,
                                   proj_w0, proj_w1, proj_w2);

    const size_t SMEM_BYTES =
        (size_t)(64 * MCOLS + 64 * 68 * 2 + 64 * 10 + 64 + 64 * 3 + MCOLS + 128) * sizeof(float);
    cudaFuncSetAttribute(edge_main_kernel,
                         cudaFuncAttributeMaxDynamicSharedMemorySize, (int)SMEM_BYTES);

    const int grid = (E + TE - 1) / TE;
    edge_main_kernel<<<grid, THREADS, SMEM_BYTES>>>(
        edge_attr, edge_scalars, edge_dst,
        rad_w1, rad_b1, rad_gamma, rad_beta,
        proj_b0, out, E);
}

// round 2
// speedup vs baseline: 1.1133x; 1.1133x over previous
#include <cuda_runtime.h>
#include <cuda_bf16.h>
#include <cstdint>

#define TE      128
#define THREADS 512
#define MCOLS   256     // padded column count (real = 224)
#define RCOLS   224
#define XPAD    132     // XG row stride (128 edges + 4 pad)

// Precomputed fused weight M[64][256] (includes diag(s), proj, and 0.25 scale)
// and bias row c[256] (includes rad_b2 contribution).
__device__ __align__(16) float g_M[64 * MCOLS];
__device__ __align__(16) float g_c[MCOLS];

// ---------------------------------------------------------------------------
// Precompute: M[k][col] = 0.25 * sum_c rad_w2[k][woff+c] * s[c] * P[c][col']
// row k==64 is the bias row (uses rad_b2 instead of rad_w2 row).
// ---------------------------------------------------------------------------
__global__ void precompute_kernel(const float* __restrict__ exp_w,
                                  const float* __restrict__ exp_b,
                                  const float* __restrict__ rad_w2,
                                  const float* __restrict__ rad_b2,
                                  const float* __restrict__ pw0,
                                  const float* __restrict__ pw1,
                                  const float* __restrict__ pw2) {
    int k   = blockIdx.x;    // 0..64 (64 = bias row)
    int col = threadIdx.x;   // 0..255
    float acc = 0.f;
    if (col < RCOLS) {
        const float* P;
        int d, woff, pstride;
        if (col < 128)      { P = pw0; d = col;       woff = 0;   pstride = 128; }
        else if (col < 192) { P = pw1; d = col - 128; woff = 128; pstride = 64;  }
        else                { P = pw2; d = col - 192; woff = 256; pstride = 32;  }
        for (int c = 0; c < 128; c++) {
            float w = (k < 64) ? rad_w2[k * 384 + woff + c] : rad_b2[woff + c];
            float s = exp_w[c] + exp_b[c];
            acc += w * s * P[c * pstride + d];
        }
        acc *= 0.25f;   // 1/sqrt(AVG_AGG)
    }
    if (k < 64) g_M[k * MCOLS + col] = acc;
    else        g_c[col] = acc;
}

// vectorized global reduction (sm_90+): 4 floats, 16B-aligned address
__device__ __forceinline__ void red4(float* p, float a, float b, float c, float d) {
    asm volatile("red.global.add.v4.f32 [%0], {%1, %2, %3, %4};"
                 :: "l"(p), "f"(a), "f"(b), "f"(c), "f"(d) : "memory");
}

__device__ __forceinline__ void cp_async16(void* smem_ptr, const void* gmem) {
    uint32_t s = (uint32_t)__cvta_generic_to_shared(smem_ptr);
    asm volatile("cp.async.cg.shared.global [%0], [%1], 16;" :: "r"(s), "l"(gmem));
}

// ---------------------------------------------------------------------------
// Main fused kernel: 1 CTA = 128 edges, 512 threads.
// Stage A: h = X @ W1 + b1 ; LN(gamma,beta) ; silu  -> g (128x64 tile)
// Stage B: t = g @ M + c                             (128x224 tile)
// Stage C: expand t via sh outer products -> red.v4 scatter into out[dst]
//          (warp-region-uniform mapping: cg = tid>>4)
// ---------------------------------------------------------------------------
__global__ __launch_bounds__(THREADS, 1)
void edge_main_kernel(const float* __restrict__ edge_attr,
                      const float* __restrict__ edge_scalars,
                      const int*   __restrict__ edge_dst,
                      const float* __restrict__ rad_w1,
                      const float* __restrict__ rad_b1,
                      const float* __restrict__ rad_gamma,
                      const float* __restrict__ rad_beta,
                      const float* __restrict__ proj_b0,
                      float* __restrict__ out,
                      int E)
{
    extern __shared__ float smem[];
    float* Ms   = smem;                    // 64*256  = 16384
    float* XG   = Ms + 64 * MCOLS;         // 64*132  = 8448  (Xt, later Gt)
    float* W1s  = XG + 64 * XPAD;          // 64*68   = 4352
    float* shS  = W1s + 64 * 68;           // 128*10  = 1280
    int*   dstS = (int*)(shS + 128 * 10);  // 128
    float* b1s  = (float*)(dstS + 128);    // 64
    float* gms  = b1s + 64;                // 64
    float* bts  = gms + 64;                // 64
    float* cS   = bts + 64;                // 256
    float* b0s  = cS + MCOLS;              // 128

    const int tid = threadIdx.x;
    const int e0  = blockIdx.x * TE;

    // ---------------- async copy of M (hidden behind stage A) ----------------
    {
        const float4* src = (const float4*)g_M;
        float4* dst4 = (float4*)Ms;
        #pragma unroll
        for (int i = 0; i < (64 * MCOLS / 4) / THREADS; i++)   // 8 iters
            cp_async16(&dst4[tid + i * THREADS], &src[tid + i * THREADS]);
        asm volatile("cp.async.commit_group;" ::: "memory");
    }

    // ---------------- load phase (sync data) ----------------
    for (int i = tid; i < 64 * 64; i += THREADS) {
        int k = i >> 6, j = i & 63;
        W1s[k * 68 + j] = rad_w1[i];
    }
    // X transposed: XG[k][e]
    for (int i4 = tid; i4 < TE * 16; i4 += THREADS) {
        int e = i4 >> 4, k4 = i4 & 15;
        int ge = e0 + e;
        float4 v = (ge < E) ? *(const float4*)&edge_scalars[(size_t)ge * 64 + k4 * 4]
                            : make_float4(0.f, 0.f, 0.f, 0.f);
        XG[(k4 * 4 + 0) * XPAD + e] = v.x;
        XG[(k4 * 4 + 1) * XPAD + e] = v.y;
        XG[(k4 * 4 + 2) * XPAD + e] = v.z;
        XG[(k4 * 4 + 3) * XPAD + e] = v.w;
    }
    for (int i = tid; i < TE * 9; i += THREADS) {
        int e = i / 9, m = i % 9;
        int ge = e0 + e;
        shS[e * 10 + m] = (ge < E) ? edge_attr[(size_t)ge * 9 + m] : 0.f;
    }
    if (tid < TE) {
        int ge = e0 + tid;
        dstS[tid] = (ge < E) ? edge_dst[ge] : 0;
    }
    if (tid < 64) { b1s[tid] = rad_b1[tid]; gms[tid] = rad_gamma[tid]; bts[tid] = rad_beta[tid]; }
    if (tid >= 64 && tid < 64 + MCOLS) cS[tid - 64] = g_c[tid - 64];
    if (tid >= 64 + MCOLS && tid < 64 + MCOLS + 128) {
        int j = tid - 64 - MCOLS;
        b0s[j] = proj_b0[j] * 0.25f;
    }
    __syncthreads();

    // ---------------- stage A: 128x64x64 GEMM + LN + silu ----------------
    {
        const int fg = tid & 15;   // feature group (4 feats)
        const int eg = tid >> 4;   // edge group (4 edges), 0..31
        float acc[4][4];
        #pragma unroll
        for (int i = 0; i < 4; i++)
            #pragma unroll
            for (int j = 0; j < 4; j++) acc[i][j] = 0.f;

        #pragma unroll 4
        for (int k = 0; k < 64; k++) {
            float4 xv = *(const float4*)&XG[k * XPAD + eg * 4];
            float4 wv = *(const float4*)&W1s[k * 68 + fg * 4];
            float xs[4] = {xv.x, xv.y, xv.z, xv.w};
            float ws[4] = {wv.x, wv.y, wv.z, wv.w};
            #pragma unroll
            for (int i = 0; i < 4; i++)
                #pragma unroll
                for (int j = 0; j < 4; j++)
                    acc[i][j] += xs[i] * ws[j];
        }

        float h[4][4], mean[4], rstd[4];
        #pragma unroll
        for (int i = 0; i < 4; i++) {
            float ps = 0.f, pq = 0.f;
            #pragma unroll
            for (int j = 0; j < 4; j++) {
                float v = acc[i][j] + b1s[fg * 4 + j];
                h[i][j] = v;
                ps += v; pq += v * v;
            }
            #pragma unroll
            for (int o = 8; o >= 1; o >>= 1) {
                ps += __shfl_xor_sync(0xffffffffu, ps, o, 16);
                pq += __shfl_xor_sync(0xffffffffu, pq, o, 16);
            }
            float mu  = ps * (1.f / 64.f);
            float var = pq * (1.f / 64.f) - mu * mu;
            mean[i] = mu;
            rstd[i] = rsqrtf(var + 1e-5f);
        }

        __syncthreads();   // all Xt reads done before overwriting XG with Gt
        #pragma unroll
        for (int i = 0; i < 4; i++) {
            #pragma unroll
            for (int j = 0; j < 4; j++) {
                int jj = fg * 4 + j;
                float v = (h[i][j] - mean[i]) * rstd[i] * gms[jj] + bts[jj];
                v = __fdividef(v, 1.f + __expf(-v));   // silu
                XG[jj * XPAD + (eg * 4 + i)] = v;      // Gt[k][e]
            }
        }
    }
    asm volatile("cp.async.wait_group 0;" ::: "memory");
    __syncthreads();

    // ---------------- stage B: 128x256x64 GEMM ----------------
    // warp-region-uniform mapping: cg = tid>>4 (8 cols), eg2 = tid&15 (8 edges)
    const int cg  = tid >> 4;   // 0..31
    const int eg2 = tid & 15;   // 0..15
    float t[8][8];
    #pragma unroll
    for (int i = 0; i < 8; i++)
        #pragma unroll
        for (int j = 0; j < 8; j++) t[i][j] = 0.f;

    #pragma unroll 2
    for (int k = 0; k < 64; k++) {
        float4 ga = *(const float4*)&XG[k * XPAD + eg2 * 8];
        float4 gb = *(const float4*)&XG[k * XPAD + eg2 * 8 + 4];
        float4 m0 = *(const float4*)&Ms[k * MCOLS + cg * 8];
        float4 m1 = *(const float4*)&Ms[k * MCOLS + cg * 8 + 4];
        float gv[8] = {ga.x, ga.y, ga.z, ga.w, gb.x, gb.y, gb.z, gb.w};
        float mv[8] = {m0.x, m0.y, m0.z, m0.w, m1.x, m1.y, m1.z, m1.w};
        #pragma unroll
        for (int i = 0; i < 8; i++)
            #pragma unroll
            for (int j = 0; j < 8; j++)
                t[i][j] += gv[i] * mv[j];
    }
    {
        float cj[8];
        #pragma unroll
        for (int j = 0; j < 8; j++) cj[j] = cS[cg * 8 + j];
        #pragma unroll
        for (int i = 0; i < 8; i++)
            #pragma unroll
            for (int j = 0; j < 8; j++) t[i][j] += cj[j];
    }

    // ---------------- stage C: expand + vector atomic scatter ----------------
    const int colbase = cg * 8;
    if (colbase < 128) {
        // region 0: y0 = sh0 * t0 + 0.25*proj_b0  (warps 0..7)
        float b0v[8];
        #pragma unroll
        for (int j = 0; j < 8; j++) b0v[j] = b0s[colbase + j];
        #pragma unroll
        for (int i = 0; i < 8; i++) {
            int e = eg2 * 8 + i;
            if (e0 + e >= E) continue;
            float s0 = shS[e * 10 + 0];
            float* base = out + (size_t)dstS[e] * 480 + colbase;
            red4(base,     fmaf(s0, t[i][0], b0v[0]), fmaf(s0, t[i][1], b0v[1]),
                           fmaf(s0, t[i][2], b0v[2]), fmaf(s0, t[i][3], b0v[3]));
            red4(base + 4, fmaf(s0, t[i][4], b0v[4]), fmaf(s0, t[i][5], b0v[5]),
                           fmaf(s0, t[i][6], b0v[6]), fmaf(s0, t[i][7], b0v[7]));
        }
    } else if (colbase < 192) {
        // region 1: y1[128 + d*3 + m] = t1[d] * sh1[m]  (warps 8..11)
        const int off = 128 + (colbase - 128) * 3;
        #pragma unroll
        for (int i = 0; i < 8; i++) {
            int e = eg2 * 8 + i;
            if (e0 + e >= E) continue;
            float s1[3] = {shS[e * 10 + 1], shS[e * 10 + 2], shS[e * 10 + 3]};
            float* base = out + (size_t)dstS[e] * 480 + off;
            #pragma unroll
            for (int g = 0; g < 6; g++) {
                const int p = g * 4;
                red4(base + p,
                     t[i][(p + 0) / 3] * s1[(p + 0) % 3],
                     t[i][(p + 1) / 3] * s1[(p + 1) % 3],
                     t[i][(p + 2) / 3] * s1[(p + 2) % 3],
                     t[i][(p + 3) / 3] * s1[(p + 3) % 3]);
            }
        }
    } else if (colbase < RCOLS) {
        // region 2: y2[320 + d*5 + m] = t2[d] * sh2[m]  (warps 12..13)
        const int off = 320 + (colbase - 192) * 5;
        #pragma unroll
        for (int i = 0; i < 8; i++) {
            int e = eg2 * 8 + i;
            if (e0 + e >= E) continue;
            float s2[5] = {shS[e * 10 + 4], shS[e * 10 + 5], shS[e * 10 + 6],
                           shS[e * 10 + 7], shS[e * 10 + 8]};
            float* base = out + (size_t)dstS[e] * 480 + off;
            #pragma unroll
            for (int g = 0; g < 10; g++) {
                const int p = g * 4;
                red4(base + p,
                     t[i][(p + 0) / 5] * s2[(p + 0) % 5],
                     t[i][(p + 1) / 5] * s2[(p + 1) % 5],
                     t[i][(p + 2) / 5] * s2[(p + 2) % 5],
                     t[i][(p + 3) / 5] * s2[(p + 3) % 5]);
            }
        }
    }
    // colbase >= 224 (warps 14,15): padding columns, nothing to emit
}

// ---------------------------------------------------------------------------
extern "C" void kernel_launch(void* const* d_in, const int* in_sizes, int n_in,
                              void* d_out, int out_size) {
    const float* edge_attr    = (const float*)d_in[1];
    const float* edge_scalars = (const float*)d_in[2];
    const int*   edge_dst     = (const int*)d_in[4];
    const float* exp_w   = (const float*)d_in[6];
    const float* exp_b   = (const float*)d_in[7];
    const float* rad_w1  = (const float*)d_in[8];
    const float* rad_b1  = (const float*)d_in[9];
    const float* rad_gamma = (const float*)d_in[10];
    const float* rad_beta  = (const float*)d_in[11];
    const float* rad_w2  = (const float*)d_in[12];
    const float* rad_b2  = (const float*)d_in[13];
    const float* proj_w0 = (const float*)d_in[14];
    const float* proj_b0 = (const float*)d_in[15];
    const float* proj_w1 = (const float*)d_in[16];
    const float* proj_w2 = (const float*)d_in[17];
    float* out = (float*)d_out;
    const int E = in_sizes[4];

    // output is poisoned; atomics need zeros
    cudaMemsetAsync(d_out, 0, (size_t)out_size * sizeof(float));

    precompute_kernel<<<65, 256>>>(exp_w, exp_b, rad_w2, rad_b2,
                                   proj_w0, proj_w1, proj_w2);

    const size_t SMEM_BYTES =
        (size_t)(64 * MCOLS + 64 * XPAD + 64 * 68 + 128 * 10 + 128 + 64 * 3 + MCOLS + 128)
        * sizeof(float);
    cudaFuncSetAttribute(edge_main_kernel,
                         cudaFuncAttributeMaxDynamicSharedMemorySize, (int)SMEM_BYTES);

    const int grid = (E + TE - 1) / TE;
    edge_main_kernel<<<grid, THREADS, SMEM_BYTES>>>(
        edge_attr, edge_scalars, edge_dst,
        rad_w1, rad_b1, rad_gamma, rad_beta,
        proj_b0, out, E);
}

// round 3
// speedup vs baseline: 1.2410x; 1.1147x over previous
#include <cuda_runtime.h>
#include <cuda_bf16.h>
#include <cstdint>

#define TE      128
#define THREADS 512
#define MCOLS   256     // padded column count (real = 224)
#define RCOLS   224
#define XPAD    132     // XG row stride (128 edges + 4 pad)
#define TSTR    228     // tS row stride in floats (128*228 == Ms+XG+W1s exactly)

// Precomputed fused weight M[64][256] (includes diag(s), proj, and 0.25 scale)
// and bias row c[256] (includes rad_b2 contribution).
__device__ __align__(16) float g_M[64 * MCOLS];
__device__ __align__(16) float g_c[MCOLS];

// ---------------------------------------------------------------------------
__global__ void precompute_kernel(const float* __restrict__ exp_w,
                                  const float* __restrict__ exp_b,
                                  const float* __restrict__ rad_w2,
                                  const float* __restrict__ rad_b2,
                                  const float* __restrict__ pw0,
                                  const float* __restrict__ pw1,
                                  const float* __restrict__ pw2) {
    int k   = blockIdx.x;    // 0..64 (64 = bias row)
    int col = threadIdx.x;   // 0..255
    float acc = 0.f;
    if (col < RCOLS) {
        const float* P;
        int d, woff, pstride;
        if (col < 128)      { P = pw0; d = col;       woff = 0;   pstride = 128; }
        else if (col < 192) { P = pw1; d = col - 128; woff = 128; pstride = 64;  }
        else                { P = pw2; d = col - 192; woff = 256; pstride = 32;  }
        for (int c = 0; c < 128; c++) {
            float w = (k < 64) ? rad_w2[k * 384 + woff + c] : rad_b2[woff + c];
            float s = exp_w[c] + exp_b[c];
            acc += w * s * P[c * pstride + d];
        }
        acc *= 0.25f;   // 1/sqrt(AVG_AGG)
    }
    if (k < 64) g_M[k * MCOLS + col] = acc;
    else        g_c[col] = acc;
}

// vectorized global reduction (sm_90+): 4 floats, 16B-aligned address
__device__ __forceinline__ void red4(float* p, float a, float b, float c, float d) {
    asm volatile("red.global.add.v4.f32 [%0], {%1, %2, %3, %4};"
                 :: "l"(p), "f"(a), "f"(b), "f"(c), "f"(d) : "memory");
}

__device__ __forceinline__ void cp_async16(void* smem_ptr, const void* gmem) {
    uint32_t s = (uint32_t)__cvta_generic_to_shared(smem_ptr);
    asm volatile("cp.async.cg.shared.global [%0], [%1], 16;" :: "r"(s), "l"(gmem));
}

// swizzled float index within a tS row: rotate the float4 index within 8-groups
__device__ __forceinline__ int swz(int col, int rot) {
    int c4 = col >> 2;
    int p4 = (c4 & ~7) | ((c4 + rot) & 7);
    return p4 * 4 + (col & 3);
}

// ---------------------------------------------------------------------------
// Main fused kernel: 1 CTA = 128 edges, 512 threads.
// Stage A: h = X @ W1 + b1 ; LN ; silu  -> g (128x64)
// Stage B: t = g @ M + c                 (128x224, cg<28 only)
// Stage C: t -> smem (swizzled), then each warp scatters 8 full edges
//          with exactly 5 red4 warp-instrs per edge (balanced).
// ---------------------------------------------------------------------------
__global__ __launch_bounds__(THREADS, 1)
void edge_main_kernel(const float* __restrict__ edge_attr,
                      const float* __restrict__ edge_scalars,
                      const int*   __restrict__ edge_dst,
                      const float* __restrict__ rad_w1,
                      const float* __restrict__ rad_b1,
                      const float* __restrict__ rad_gamma,
                      const float* __restrict__ rad_beta,
                      const float* __restrict__ proj_b0,
                      float* __restrict__ out,
                      int E)
{
    extern __shared__ float smem[];
    float* Ms   = smem;                    // 64*256  = 16384 ┐
    float* XG   = Ms + 64 * MCOLS;         // 64*132  = 8448  ├ aliased by tS[128][228]
    float* W1s  = XG + 64 * XPAD;          // 64*68   = 4352  ┘ (29184 floats total)
    float* shS  = W1s + 64 * 68;           // 128*10  = 1280
    int*   dstS = (int*)(shS + 128 * 10);  // 128
    float* b1s  = (float*)(dstS + 128);    // 64
    float* gms  = b1s + 64;                // 64
    float* bts  = gms + 64;                // 64
    float* cS   = bts + 64;                // 256
    float* b0s  = cS + MCOLS;              // 128
    float* tS   = smem;                    // alias (valid after stage B)

    const int tid = threadIdx.x;
    const int e0  = blockIdx.x * TE;

    // ---------------- async copy of M (hidden behind stage A) ----------------
    {
        const float4* src = (const float4*)g_M;
        float4* dst4 = (float4*)Ms;
        #pragma unroll
        for (int i = 0; i < (64 * MCOLS / 4) / THREADS; i++)   // 8 iters
            cp_async16(&dst4[tid + i * THREADS], &src[tid + i * THREADS]);
        asm volatile("cp.async.commit_group;" ::: "memory");
    }

    // ---------------- load phase ----------------
    for (int i = tid; i < 64 * 64; i += THREADS) {
        int k = i >> 6, j = i & 63;
        W1s[k * 68 + j] = rad_w1[i];
    }
    for (int i4 = tid; i4 < TE * 16; i4 += THREADS) {
        int e = i4 >> 4, k4 = i4 & 15;
        int ge = e0 + e;
        float4 v = (ge < E) ? *(const float4*)&edge_scalars[(size_t)ge * 64 + k4 * 4]
                            : make_float4(0.f, 0.f, 0.f, 0.f);
        XG[(k4 * 4 + 0) * XPAD + e] = v.x;
        XG[(k4 * 4 + 1) * XPAD + e] = v.y;
        XG[(k4 * 4 + 2) * XPAD + e] = v.z;
        XG[(k4 * 4 + 3) * XPAD + e] = v.w;
    }
    for (int i = tid; i < TE * 9; i += THREADS) {
        int e = i / 9, m = i % 9;
        int ge = e0 + e;
        shS[e * 10 + m] = (ge < E) ? edge_attr[(size_t)ge * 9 + m] : 0.f;
    }
    if (tid < TE) {
        int ge = e0 + tid;
        dstS[tid] = (ge < E) ? edge_dst[ge] : 0;
    }
    if (tid < 64) { b1s[tid] = rad_b1[tid]; gms[tid] = rad_gamma[tid]; bts[tid] = rad_beta[tid]; }
    if (tid >= 64 && tid < 64 + MCOLS) cS[tid - 64] = g_c[tid - 64];
    if (tid >= 64 + MCOLS && tid < 64 + MCOLS + 128) {
        int j = tid - 64 - MCOLS;
        b0s[j] = proj_b0[j] * 0.25f;
    }
    __syncthreads();

    // ---------------- stage A: 128x64x64 GEMM + LN + silu ----------------
    {
        const int fg = tid & 15;   // 4 feats
        const int eg = tid >> 4;   // 4 edges, 0..31
        float acc[4][4];
        #pragma unroll
        for (int i = 0; i < 4; i++)
            #pragma unroll
            for (int j = 0; j < 4; j++) acc[i][j] = 0.f;

        #pragma unroll 4
        for (int k = 0; k < 64; k++) {
            float4 xv = *(const float4*)&XG[k * XPAD + eg * 4];
            float4 wv = *(const float4*)&W1s[k * 68 + fg * 4];
            float xs[4] = {xv.x, xv.y, xv.z, xv.w};
            float ws[4] = {wv.x, wv.y, wv.z, wv.w};
            #pragma unroll
            for (int i = 0; i < 4; i++)
                #pragma unroll
                for (int j = 0; j < 4; j++)
                    acc[i][j] += xs[i] * ws[j];
        }

        float h[4][4], mean[4], rstd[4];
        #pragma unroll
        for (int i = 0; i < 4; i++) {
            float ps = 0.f, pq = 0.f;
            #pragma unroll
            for (int j = 0; j < 4; j++) {
                float v = acc[i][j] + b1s[fg * 4 + j];
                h[i][j] = v;
                ps += v; pq += v * v;
            }
            #pragma unroll
            for (int o = 8; o >= 1; o >>= 1) {
                ps += __shfl_xor_sync(0xffffffffu, ps, o, 16);
                pq += __shfl_xor_sync(0xffffffffu, pq, o, 16);
            }
            float mu  = ps * (1.f / 64.f);
            float var = pq * (1.f / 64.f) - mu * mu;
            mean[i] = mu;
            rstd[i] = rsqrtf(var + 1e-5f);
        }

        __syncthreads();   // Xt reads done before overwriting XG with Gt
        #pragma unroll
        for (int i = 0; i < 4; i++) {
            #pragma unroll
            for (int j = 0; j < 4; j++) {
                int jj = fg * 4 + j;
                float v = (h[i][j] - mean[i]) * rstd[i] * gms[jj] + bts[jj];
                v = __fdividef(v, 1.f + __expf(-v));   // silu
                XG[jj * XPAD + (eg * 4 + i)] = v;      // Gt[k][e]
            }
        }
    }
    asm volatile("cp.async.wait_group 0;" ::: "memory");
    __syncthreads();

    // ---------------- stage B: 128x224x64 GEMM (cg<28) ----------------
    const int cg  = tid >> 4;   // 0..31 (28..31 = padding, skip)
    const int eg2 = tid & 15;   // 0..15
    float t[8][8];
    if (cg < 28) {
        #pragma unroll
        for (int i = 0; i < 8; i++)
            #pragma unroll
            for (int j = 0; j < 8; j++) t[i][j] = 0.f;

        #pragma unroll 2
        for (int k = 0; k < 64; k++) {
            float4 ga = *(const float4*)&XG[k * XPAD + eg2 * 8];
            float4 gb = *(const float4*)&XG[k * XPAD + eg2 * 8 + 4];
            float4 m0 = *(const float4*)&Ms[k * MCOLS + cg * 8];
            float4 m1 = *(const float4*)&Ms[k * MCOLS + cg * 8 + 4];
            float gv[8] = {ga.x, ga.y, ga.z, ga.w, gb.x, gb.y, gb.z, gb.w};
            float mv[8] = {m0.x, m0.y, m0.z, m0.w, m1.x, m1.y, m1.z, m1.w};
            #pragma unroll
            for (int i = 0; i < 8; i++)
                #pragma unroll
                for (int j = 0; j < 8; j++)
                    t[i][j] += gv[i] * mv[j];
        }
        float cj[8];
        #pragma unroll
        for (int j = 0; j < 8; j++) cj[j] = cS[cg * 8 + j];
        #pragma unroll
        for (int i = 0; i < 8; i++)
            #pragma unroll
            for (int j = 0; j < 8; j++) t[i][j] += cj[j];
    }
    __syncthreads();   // all stage-B reads of Ms/XG complete

    // ---------------- stage C part 1: stage t into smem (swizzled) ----------
    if (cg < 28) {
        const int rot = eg2 & 7;
        const int c40 = cg * 2;
        const int p0 = (c40 & ~7) | ((c40 + rot) & 7);
        const int p1 = ((c40 + 1) & ~7) | ((c40 + 1 + rot) & 7);
        #pragma unroll
        for (int i = 0; i < 8; i++) {
            int e = eg2 * 8 + i;
            *(float4*)&tS[e * TSTR + p0 * 4] = make_float4(t[i][0], t[i][1], t[i][2], t[i][3]);
            *(float4*)&tS[e * TSTR + p1 * 4] = make_float4(t[i][4], t[i][5], t[i][6], t[i][7]);
        }
    }
    __syncthreads();

    // ---------------- stage C part 2: balanced scatter, 1 warp = 8 edges ----
    {
        const int w = tid >> 5;    // 0..15
        const int l = tid & 31;
        const float4 b0v = *(const float4*)&b0s[l * 4];

        #pragma unroll 1
        for (int i = 0; i < 8; i++) {
            const int e = w * 8 + i;
            if (e0 + e >= E) continue;
            const int rot = (e >> 3) & 7;
            const float* te = &tS[e * TSTR];
            const float* sh = &shS[e * 10];
            float* base = out + (size_t)dstS[e] * 480;
            const float s0 = sh[0];

            // region 0: 32 red4 (one per lane), cols 0..127
            {
                int pc = (l & ~7) | ((l + rot) & 7);
                float4 v = *(const float4*)&te[pc * 4];
                red4(base + l * 4,
                     fmaf(s0, v.x, b0v.x), fmaf(s0, v.y, b0v.y),
                     fmaf(s0, v.z, b0v.z), fmaf(s0, v.w, b0v.w));
            }
            // region 1: 48 red4 over lanes (2 rounds), y1[p] = t1[(p)/3]*sh1[p%3]
            #pragma unroll
            for (int r = 0; r < 2; r++) {
                int j = l + r * 32;
                if (j < 48) {
                    int p = 4 * j;
                    int q = (p * 0x5556) >> 16;          // p/3 (p<192)
                    int m = p - 3 * q;                   // p%3
                    float ta = te[swz(128 + q, rot)];
                    float tb = te[swz(128 + q + 1, rot)];
                    float v[4];
                    #pragma unroll
                    for (int ii = 0; ii < 4; ii++) {
                        int mi = m + ii;
                        int f  = (mi >= 3);
                        float sv = sh[1 + mi - 3 * f];
                        v[ii] = (f ? tb : ta) * sv;
                    }
                    red4(base + 128 + p, v[0], v[1], v[2], v[3]);
                }
            }
            // region 2: 40 red4 over lanes (2 rounds), y2[p] = t2[p/5]*sh2[p%5]
            #pragma unroll
            for (int r = 0; r < 2; r++) {
                int j = l + r * 32;
                if (j < 40) {
                    int p = 4 * j;
                    int q = (p * 0x3334) >> 16;          // p/5 (p<160)
                    int m = p - 5 * q;                   // p%5
                    int qb = (q + 1 > 31) ? 31 : q + 1;  // clamp (unused when OOB)
                    float ta = te[swz(192 + q, rot)];
                    float tb = te[swz(192 + qb, rot)];
                    float v[4];
                    #pragma unroll
                    for (int ii = 0; ii < 4; ii++) {
                        int mi = m + ii;
                        int f  = (mi >= 5);
                        float sv = sh[4 + mi - 5 * f];
                        v[ii] = (f ? tb : ta) * sv;
                    }
                    red4(base + 320 + p, v[0], v[1], v[2], v[3]);
                }
            }
        }
    }
}

// ---------------------------------------------------------------------------
extern "C" void kernel_launch(void* const* d_in, const int* in_sizes, int n_in,
                              void* d_out, int out_size) {
    const float* edge_attr    = (const float*)d_in[1];
    const float* edge_scalars = (const float*)d_in[2];
    const int*   edge_dst     = (const int*)d_in[4];
    const float* exp_w   = (const float*)d_in[6];
    const float* exp_b   = (const float*)d_in[7];
    const float* rad_w1  = (const float*)d_in[8];
    const float* rad_b1  = (const float*)d_in[9];
    const float* rad_gamma = (const float*)d_in[10];
    const float* rad_beta  = (const float*)d_in[11];
    const float* rad_w2  = (const float*)d_in[12];
    const float* rad_b2  = (const float*)d_in[13];
    const float* proj_w0 = (const float*)d_in[14];
    const float* proj_b0 = (const float*)d_in[15];
    const float* proj_w1 = (const float*)d_in[16];
    const float* proj_w2 = (const float*)d_in[17];
    float* out = (float*)d_out;
    const int E = in_sizes[4];

    cudaMemsetAsync(d_out, 0, (size_t)out_size * sizeof(float));

    precompute_kernel<<<65, 256>>>(exp_w, exp_b, rad_w2, rad_b2,
                                   proj_w0, proj_w1, proj_w2);

    const size_t SMEM_BYTES =
        (size_t)(64 * MCOLS + 64 * XPAD + 64 * 68 + 128 * 10 + 128 + 64 * 3 + MCOLS + 128)
        * sizeof(float);
    cudaFuncSetAttribute(edge_main_kernel,
                         cudaFuncAttributeMaxDynamicSharedMemorySize, (int)SMEM_BYTES);

    const int grid = (E + TE - 1) / TE;
    edge_main_kernel<<<grid, THREADS, SMEM_BYTES>>>(
        edge_attr, edge_scalars, edge_dst,
        rad_w1, rad_b1, rad_gamma, rad_beta,
        proj_b0, out, E);
}

// round 4
// speedup vs baseline: 2.2186x; 1.7877x over previous
#include <cuda_runtime.h>
#include <cuda_bf16.h>
#include <cstdint>

#define TE      128
#define THREADS 512
#define RCOLS   224
#define MSTR    264     // Ms smem row stride (mod 32 == 8 -> conflict-free B frags)
#define XSTR    68      // Xs row stride (mod 32 == 4 -> conflict-free A frags)
#define GSTR    68
#define W1STR   72      // W1 row stride (mod 32 == 8)
#define TSTR    228     // t staging row stride

// Precomputed fused weight M[64][256] (tf32 bits; includes diag(s), proj, 0.25),
// bias row c[256] (fp32), and tf32-rounded W1.
__device__ __align__(16) float g_M[64 * 256];
__device__ __align__(16) float g_c[256];
__device__ __align__(16) float g_W1[64 * 64];

__device__ __forceinline__ uint32_t f2tf32(float f) {
    uint32_t u;
    asm("cvt.rna.tf32.f32 %0, %1;" : "=r"(u) : "f"(f));
    return u;
}

// ---------------------------------------------------------------------------
__global__ void precompute_kernel(const float* __restrict__ exp_w,
                                  const float* __restrict__ exp_b,
                                  const float* __restrict__ rad_w2,
                                  const float* __restrict__ rad_b2,
                                  const float* __restrict__ pw0,
                                  const float* __restrict__ pw1,
                                  const float* __restrict__ pw2) {
    int k   = blockIdx.x;    // 0..64 (64 = bias row)
    int col = threadIdx.x;   // 0..255
    float acc = 0.f;
    if (col < RCOLS) {
        const float* P;
        int d, woff, pstride;
        if (col < 128)      { P = pw0; d = col;       woff = 0;   pstride = 128; }
        else if (col < 192) { P = pw1; d = col - 128; woff = 128; pstride = 64;  }
        else                { P = pw2; d = col - 192; woff = 256; pstride = 32;  }
        for (int c = 0; c < 128; c++) {
            float w = (k < 64) ? rad_w2[k * 384 + woff + c] : rad_b2[woff + c];
            float s = exp_w[c] + exp_b[c];
            acc += w * s * P[c * pstride + d];
        }
        acc *= 0.25f;   // 1/sqrt(AVG_AGG)
    }
    if (k < 64) g_M[k * 256 + col] = __uint_as_float(f2tf32(acc));  // tf32 bits
    else        g_c[col] = acc;                                     // fp32 bias
}

__global__ void w1_prep_kernel(const float* __restrict__ rad_w1) {
    int i = blockIdx.x * 256 + threadIdx.x;
    if (i < 64 * 64) g_W1[i] = __uint_as_float(f2tf32(rad_w1[i]));
}

// ---------------------------------------------------------------------------
__device__ __forceinline__ void red4(float* p, float a, float b, float c, float d) {
    asm volatile("red.global.add.v4.f32 [%0], {%1, %2, %3, %4};"
                 :: "l"(p), "f"(a), "f"(b), "f"(c), "f"(d) : "memory");
}

__device__ __forceinline__ void cp_async16(void* smem_ptr, const void* gmem) {
    uint32_t s = (uint32_t)__cvta_generic_to_shared(smem_ptr);
    asm volatile("cp.async.cg.shared.global [%0], [%1], 16;" :: "r"(s), "l"(gmem));
}
__device__ __forceinline__ void cp_async16_zfill(void* smem_ptr, const void* gmem, int srcsz) {
    uint32_t s = (uint32_t)__cvta_generic_to_shared(smem_ptr);
    asm volatile("cp.async.cg.shared.global [%0], [%1], 16, %2;"
                 :: "r"(s), "l"(gmem), "r"(srcsz));
}

__device__ __forceinline__ void mma_tf32(float d[4], const uint32_t a[4],
                                         uint32_t b0, uint32_t b1) {
    asm volatile(
        "mma.sync.aligned.m16n8k8.row.col.f32.tf32.tf32.f32 "
        "{%0,%1,%2,%3}, {%4,%5,%6,%7}, {%8,%9}, {%0,%1,%2,%3};"
        : "+f"(d[0]), "+f"(d[1]), "+f"(d[2]), "+f"(d[3])
        : "r"(a[0]), "r"(a[1]), "r"(a[2]), "r"(a[3]), "r"(b0), "r"(b1));
}

// ---------------------------------------------------------------------------
// 1 CTA = 128 edges, 512 threads, tensor-core GEMMs.
// Stage A: h = X @ W1 (mma tf32) -> LN+silu -> G (tf32 bits in smem)
// Stage B: t = G @ M + c (mma tf32)
// Stage C: balanced red.v4 scatter (1 warp = 8 edges, 5 red4/edge)
// ---------------------------------------------------------------------------
__global__ __launch_bounds__(THREADS, 1)
void edge_main_kernel(const float* __restrict__ edge_attr,
                      const float* __restrict__ edge_scalars,
                      const int*   __restrict__ edge_dst,
                      const float* __restrict__ rad_b1,
                      const float* __restrict__ rad_gamma,
                      const float* __restrict__ rad_beta,
                      const float* __restrict__ proj_b0,
                      float* __restrict__ out,
                      int E)
{
    extern __shared__ float smem[];
    float* Ms   = smem;                     // 64*264 = 16896 ┐
    float* Xs   = Ms + 64 * MSTR;           // 128*68 = 8704  ├ aliased by tS[128][228]
    float* Gs   = Xs + 128 * XSTR;          // 128*68 = 8704  ┘ (34304 total >= 29184)
    float* W1s  = Gs + 128 * GSTR;          // 64*72  = 4608
    float* shS  = W1s + 64 * W1STR;         // 128*10 = 1280
    int*   dstS = (int*)(shS + 128 * 10);   // 128
    float* b1s  = (float*)(dstS + 128);     // 64
    float* gms  = b1s + 64;                 // 64
    float* bts  = gms + 64;                 // 64
    float* cS   = bts + 64;                 // 256
    float* b0s  = cS + 256;                 // 128
    float* tS   = smem;                     // alias, valid after stage B

    const int tid = threadIdx.x;
    const int l   = tid & 31;
    const int w   = tid >> 5;
    const int e0  = blockIdx.x * TE;

    // -------- async loads: group1 = Xs + W1s ; group2 = Ms --------
    for (int i = tid; i < TE * 16; i += THREADS) {
        int e = i >> 4, c4 = i & 15;
        int ge = e0 + e;
        int gc = (ge < E) ? ge : (E - 1);
        cp_async16_zfill(&Xs[e * XSTR + c4 * 4],
                         edge_scalars + (size_t)gc * 64 + c4 * 4,
                         (ge < E) ? 16 : 0);
    }
    for (int i = tid; i < 64 * 16; i += THREADS) {
        int k = i >> 4, c4 = i & 15;
        cp_async16(&W1s[k * W1STR + c4 * 4], &g_W1[k * 64 + c4 * 4]);
    }
    asm volatile("cp.async.commit_group;" ::: "memory");
    for (int i = tid; i < 64 * 64; i += THREADS) {
        int k = i >> 6, c4 = i & 63;
        cp_async16(&Ms[k * MSTR + c4 * 4], &g_M[k * 256 + c4 * 4]);
    }
    asm volatile("cp.async.commit_group;" ::: "memory");

    // -------- small scalar loads --------
    for (int i = tid; i < TE * 9; i += THREADS) {
        int e = i / 9, m = i % 9;
        int ge = e0 + e;
        shS[e * 10 + m] = (ge < E) ? edge_attr[(size_t)ge * 9 + m] : 0.f;
    }
    if (tid < TE) {
        int ge = e0 + tid;
        dstS[tid] = (ge < E) ? edge_dst[ge] : 0;
    }
    if (tid < 64) { b1s[tid] = rad_b1[tid]; gms[tid] = rad_gamma[tid]; bts[tid] = rad_beta[tid]; }
    if (tid >= 64 && tid < 64 + 256) cS[tid - 64] = g_c[tid - 64];
    if (tid >= 320 && tid < 448) b0s[tid - 320] = proj_b0[tid - 320] * 0.25f;

    asm volatile("cp.async.wait_group 1;" ::: "memory");
    __syncthreads();

    // -------- stage A: h[128x64] = X @ W1 (mma tf32) --------
    {
        const int mt = w >> 1;           // m-tile 0..7
        const int nq = w & 1;            // n half
        const int m0 = mt * 16;
        float d[4][4] = {};
        const int ar0 = (m0 + (l >> 2)) * XSTR + (l & 3);
        const int ar1 = ar0 + 8 * XSTR;
        const uint32_t* W1u = (const uint32_t*)W1s;

        #pragma unroll
        for (int k0 = 0; k0 < 64; k0 += 8) {
            uint32_t a[4];
            a[0] = f2tf32(Xs[ar0 + k0]);
            a[1] = f2tf32(Xs[ar1 + k0]);
            a[2] = f2tf32(Xs[ar0 + k0 + 4]);
            a[3] = f2tf32(Xs[ar1 + k0 + 4]);
            #pragma unroll
            for (int nt = 0; nt < 4; nt++) {
                int n0 = (nq * 4 + nt) * 8;
                uint32_t b0 = W1u[(k0 + (l & 3)) * W1STR + n0 + (l >> 2)];
                uint32_t b1 = W1u[(k0 + (l & 3) + 4) * W1STR + n0 + (l >> 2)];
                mma_tf32(d[nt], a, b0, b1);
            }
        }
        // stash raw h into Gs (fp32)
        #pragma unroll
        for (int nt = 0; nt < 4; nt++) {
            int c  = (nq * 4 + nt) * 8 + (l & 3) * 2;
            int r0 = m0 + (l >> 2);
            *(float2*)&Gs[r0 * GSTR + c]       = make_float2(d[nt][0], d[nt][1]);
            *(float2*)&Gs[(r0 + 8) * GSTR + c] = make_float2(d[nt][2], d[nt][3]);
        }
    }
    __syncthreads();

    // -------- LN + silu + tf32 convert (in place on Gs) --------
    {
        const int row = tid >> 2;       // 0..127
        const int qd  = tid & 3;        // 16-col quarter
        float* hp = &Gs[row * GSTR + qd * 16];
        float v[16];
        float ps = 0.f, pq = 0.f;
        #pragma unroll
        for (int j = 0; j < 4; j++) {
            float4 x = ((const float4*)hp)[j];
            float b0 = b1s[qd * 16 + j * 4 + 0], b1 = b1s[qd * 16 + j * 4 + 1];
            float b2 = b1s[qd * 16 + j * 4 + 2], b3 = b1s[qd * 16 + j * 4 + 3];
            v[j * 4 + 0] = x.x + b0; v[j * 4 + 1] = x.y + b1;
            v[j * 4 + 2] = x.z + b2; v[j * 4 + 3] = x.w + b3;
            #pragma unroll
            for (int u = 0; u < 4; u++) { ps += v[j * 4 + u]; pq += v[j * 4 + u] * v[j * 4 + u]; }
        }
        ps += __shfl_xor_sync(0xffffffffu, ps, 1);
        pq += __shfl_xor_sync(0xffffffffu, pq, 1);
        ps += __shfl_xor_sync(0xffffffffu, ps, 2);
        pq += __shfl_xor_sync(0xffffffffu, pq, 2);
        float mu   = ps * (1.f / 64.f);
        float var  = pq * (1.f / 64.f) - mu * mu;
        float rstd = rsqrtf(var + 1e-5f);
        uint32_t o[16];
        #pragma unroll
        for (int u = 0; u < 16; u++) {
            int jj = qd * 16 + u;
            float g = (v[u] - mu) * rstd * gms[jj] + bts[jj];
            g = __fdividef(g, 1.f + __expf(-g));   // silu
            o[u] = f2tf32(g);
        }
        #pragma unroll
        for (int j = 0; j < 4; j++)
            ((uint4*)hp)[j] = make_uint4(o[j * 4], o[j * 4 + 1], o[j * 4 + 2], o[j * 4 + 3]);
    }
    asm volatile("cp.async.wait_group 0;" ::: "memory");
    __syncthreads();

    // -------- stage B: t[128x224] = G @ M + c (mma tf32) --------
    {
        const int mg = w & 3;            // m-pair group (rows mg*32 .. +31)
        const int ng = w >> 2;           // n group (cols ng*56 .. +55)
        const int m0 = mg * 32;
        const int n0 = ng * 56;
        float d[2][7][4] = {};
        const uint32_t* Gu = (const uint32_t*)Gs;
        const uint32_t* Mu = (const uint32_t*)Ms;
        const int ar00 = (m0 + (l >> 2)) * GSTR + (l & 3);

        #pragma unroll
        for (int k0 = 0; k0 < 64; k0 += 8) {
            uint32_t a[2][4];
            #pragma unroll
            for (int mt = 0; mt < 2; mt++) {
                int base = ar00 + mt * 16 * GSTR + k0;
                a[mt][0] = Gu[base];
                a[mt][1] = Gu[base + 8 * GSTR];
                a[mt][2] = Gu[base + 4];
                a[mt][3] = Gu[base + 8 * GSTR + 4];
            }
            const int brow = (k0 + (l & 3)) * MSTR + n0 + (l >> 2);
            #pragma unroll
            for (int jt = 0; jt < 7; jt++) {
                uint32_t b0 = Mu[brow + jt * 8];
                uint32_t b1 = Mu[brow + 4 * MSTR + jt * 8];
                mma_tf32(d[0][jt], a[0], b0, b1);
                mma_tf32(d[1][jt], a[1], b0, b1);
            }
        }
        __syncthreads();   // all mma reads of Ms/Gs done before tS overwrites them

        #pragma unroll
        for (int jt = 0; jt < 7; jt++) {
            int c = n0 + jt * 8 + (l & 3) * 2;
            float c0 = cS[c], c1 = cS[c + 1];
            #pragma unroll
            for (int mt = 0; mt < 2; mt++) {
                int r0 = m0 + mt * 16 + (l >> 2);
                *(float2*)&tS[r0 * TSTR + c] =
                    make_float2(d[mt][jt][0] + c0, d[mt][jt][1] + c1);
                *(float2*)&tS[(r0 + 8) * TSTR + c] =
                    make_float2(d[mt][jt][2] + c0, d[mt][jt][3] + c1);
            }
        }
    }
    __syncthreads();

    // -------- stage C: balanced scatter, 1 warp = 8 edges --------
    {
        const float4 b0v = *(const float4*)&b0s[l * 4];
        #pragma unroll 1
        for (int i = 0; i < 8; i++) {
            const int e = w * 8 + i;
            if (e0 + e >= E) continue;
            const float* te = &tS[e * TSTR];
            const float* sh = &shS[e * 10];
            float* base = out + (size_t)dstS[e] * 480;
            const float s0 = sh[0];

            // region 0: cols 0..127
            {
                float4 v = *(const float4*)&te[l * 4];
                red4(base + l * 4,
                     fmaf(s0, v.x, b0v.x), fmaf(s0, v.y, b0v.y),
                     fmaf(s0, v.z, b0v.z), fmaf(s0, v.w, b0v.w));
            }
            // region 1: y1[p] = t1[p/3] * sh1[p%3], 192 floats
            #pragma unroll
            for (int r = 0; r < 2; r++) {
                int j = l + r * 32;
                if (j < 48) {
                    int p = 4 * j;
                    int q = (p * 0x5556) >> 16;
                    int m = p - 3 * q;
                    float ta = te[128 + q];
                    float tb = te[128 + q + 1];
                    float v[4];
                    #pragma unroll
                    for (int ii = 0; ii < 4; ii++) {
                        int mi = m + ii;
                        int f  = (mi >= 3);
                        float sv = sh[1 + mi - 3 * f];
                        v[ii] = (f ? tb : ta) * sv;
                    }
                    red4(base + 128 + p, v[0], v[1], v[2], v[3]);
                }
            }
            // region 2: y2[p] = t2[p/5] * sh2[p%5], 160 floats
            #pragma unroll
            for (int r = 0; r < 2; r++) {
                int j = l + r * 32;
                if (j < 40) {
                    int p = 4 * j;
                    int q = (p * 0x3334) >> 16;
                    int m = p - 5 * q;
                    int qb = (q + 1 > 31) ? 31 : q + 1;
                    float ta = te[192 + q];
                    float tb = te[192 + qb];
                    float v[4];
                    #pragma unroll
                    for (int ii = 0; ii < 4; ii++) {
                        int mi = m + ii;
                        int f  = (mi >= 5);
                        float sv = sh[4 + mi - 5 * f];
                        v[ii] = (f ? tb : ta) * sv;
                    }
                    red4(base + 320 + p, v[0], v[1], v[2], v[3]);
                }
            }
        }
    }
}

// ---------------------------------------------------------------------------
extern "C" void kernel_launch(void* const* d_in, const int* in_sizes, int n_in,
                              void* d_out, int out_size) {
    const float* edge_attr    = (const float*)d_in[1];
    const float* edge_scalars = (const float*)d_in[2];
    const int*   edge_dst     = (const int*)d_in[4];
    const float* exp_w   = (const float*)d_in[6];
    const float* exp_b   = (const float*)d_in[7];
    const float* rad_w1  = (const float*)d_in[8];
    const float* rad_b1  = (const float*)d_in[9];
    const float* rad_gamma = (const float*)d_in[10];
    const float* rad_beta  = (const float*)d_in[11];
    const float* rad_w2  = (const float*)d_in[12];
    const float* rad_b2  = (const float*)d_in[13];
    const float* proj_w0 = (const float*)d_in[14];
    const float* proj_b0 = (const float*)d_in[15];
    const float* proj_w1 = (const float*)d_in[16];
    const float* proj_w2 = (const float*)d_in[17];
    float* out = (float*)d_out;
    const int E = in_sizes[4];

    cudaMemsetAsync(d_out, 0, (size_t)out_size * sizeof(float));

    precompute_kernel<<<65, 256>>>(exp_w, exp_b, rad_w2, rad_b2,
                                   proj_w0, proj_w1, proj_w2);
    w1_prep_kernel<<<16, 256>>>(rad_w1);

    const size_t SMEM_FLOATS =
        64 * MSTR + 128 * XSTR + 128 * GSTR + 64 * W1STR +
        128 * 10 + 128 + 64 * 3 + 256 + 128;
    const size_t SMEM_BYTES = SMEM_FLOATS * sizeof(float);
    cudaFuncSetAttribute(edge_main_kernel,
                         cudaFuncAttributeMaxDynamicSharedMemorySize, (int)SMEM_BYTES);

    const int grid = (E + TE - 1) / TE;
    edge_main_kernel<<<grid, THREADS, SMEM_BYTES>>>(
        edge_attr, edge_scalars, edge_dst,
        rad_b1, rad_gamma, rad_beta,
        proj_b0, out, E);
}

// round 5
// speedup vs baseline: 2.4940x; 1.1241x over previous
#include <cuda_runtime.h>
#include <cuda_bf16.h>
#include <cstdint>

#define THREADS 512
#define RCOLS   224
#define MSTR    264     // Ms smem row stride (mod 32 == 8 -> conflict-free B frags)
#define XSTR    68      // Xs row stride (mod 32 == 4 -> conflict-free A frags)
#define GSTR    68
#define W1STR   72      // W1 row stride (mod 32 == 8)
#define TSTR    228     // t staging row stride (64 rows per half)

// Precomputed fused weight M[64][256] (tf32 bits; includes diag(s), proj, 0.25),
// bias row c[256] (fp32), and tf32-rounded W1.
__device__ __align__(16) float g_M[64 * 256];
__device__ __align__(16) float g_c[256];
__device__ __align__(16) float g_W1[64 * 64];

__device__ __forceinline__ uint32_t f2tf32(float f) {
    uint32_t u;
    asm("cvt.rna.tf32.f32 %0, %1;" : "=r"(u) : "f"(f));
    return u;
}

// ---------------------------------------------------------------------------
// Precompute with smem-cached s and w-row, unrolled (latency fix).
// ---------------------------------------------------------------------------
__global__ void precompute_kernel(const float* __restrict__ exp_w,
                                  const float* __restrict__ exp_b,
                                  const float* __restrict__ rad_w2,
                                  const float* __restrict__ rad_b2,
                                  const float* __restrict__ pw0,
                                  const float* __restrict__ pw1,
                                  const float* __restrict__ pw2) {
    __shared__ float s_s[128];
    __shared__ float s_w[384];
    int k   = blockIdx.x;    // 0..64 (64 = bias row)
    int col = threadIdx.x;   // 0..255
    if (col < 128) s_s[col] = exp_w[col] + exp_b[col];
    for (int i = col; i < 384; i += 256)
        s_w[i] = (k < 64) ? rad_w2[k * 384 + i] : rad_b2[i];
    __syncthreads();

    float acc = 0.f;
    if (col < RCOLS) {
        const float* P;
        int d, woff, pstride;
        if (col < 128)      { P = pw0; d = col;       woff = 0;   pstride = 128; }
        else if (col < 192) { P = pw1; d = col - 128; woff = 128; pstride = 64;  }
        else                { P = pw2; d = col - 192; woff = 256; pstride = 32;  }
        #pragma unroll 8
        for (int c = 0; c < 128; c++)
            acc += s_w[woff + c] * s_s[c] * P[c * pstride + d];
        acc *= 0.25f;   // 1/sqrt(AVG_AGG)
    }
    if (k < 64) g_M[k * 256 + col] = __uint_as_float(f2tf32(acc));  // tf32 bits
    else        g_c[col] = acc;                                     // fp32 bias
}

__global__ void w1_prep_kernel(const float* __restrict__ rad_w1) {
    int i = blockIdx.x * 256 + threadIdx.x;
    if (i < 64 * 64) g_W1[i] = __uint_as_float(f2tf32(rad_w1[i]));
}

// ---------------------------------------------------------------------------
__device__ __forceinline__ void red4(float* p, float a, float b, float c, float d) {
    asm volatile("red.global.add.v4.f32 [%0], {%1, %2, %3, %4};"
                 :: "l"(p), "f"(a), "f"(b), "f"(c), "f"(d) : "memory");
}

__device__ __forceinline__ void cp_async16(void* smem_ptr, const void* gmem) {
    uint32_t s = (uint32_t)__cvta_generic_to_shared(smem_ptr);
    asm volatile("cp.async.cg.shared.global [%0], [%1], 16;" :: "r"(s), "l"(gmem));
}
__device__ __forceinline__ void cp_async16_zfill(void* smem_ptr, const void* gmem, int srcsz) {
    uint32_t s = (uint32_t)__cvta_generic_to_shared(smem_ptr);
    asm volatile("cp.async.cg.shared.global [%0], [%1], 16, %2;"
                 :: "r"(s), "l"(gmem), "r"(srcsz));
}
__device__ __forceinline__ void cp_async4_zfill(void* smem_ptr, const void* gmem, int srcsz) {
    uint32_t s = (uint32_t)__cvta_generic_to_shared(smem_ptr);
    asm volatile("cp.async.ca.shared.global [%0], [%1], 4, %2;"
                 :: "r"(s), "l"(gmem), "r"(srcsz));
}

__device__ __forceinline__ void mma_tf32(float d[4], const uint32_t a[4],
                                         uint32_t b0, uint32_t b1) {
    asm volatile(
        "mma.sync.aligned.m16n8k8.row.col.f32.tf32.tf32.f32 "
        "{%0,%1,%2,%3}, {%4,%5,%6,%7}, {%8,%9}, {%0,%1,%2,%3};"
        : "+f"(d[0]), "+f"(d[1]), "+f"(d[2]), "+f"(d[3])
        : "r"(a[0]), "r"(a[1]), "r"(a[2]), "r"(a[3]), "r"(b0), "r"(b1));
}

// ---------------------------------------------------------------------------
// Persistent kernel: each CTA loops over 128-edge tiles (stride gridDim).
// M/W1 loaded once; next-tile X/sh/dst prefetched behind LN+stageB+scatter.
// ---------------------------------------------------------------------------
__global__ __launch_bounds__(THREADS, 1)
void edge_main_kernel(const float* __restrict__ edge_attr,
                      const float* __restrict__ edge_scalars,
                      const int*   __restrict__ edge_dst,
                      const float* __restrict__ rad_b1,
                      const float* __restrict__ rad_gamma,
                      const float* __restrict__ rad_beta,
                      const float* __restrict__ proj_b0,
                      float* __restrict__ out,
                      int E, int nTiles)
{
    extern __shared__ float smem[];
    float* Ms   = smem;                     // 16896
    float* W1s  = Ms + 64 * MSTR;           // 4608
    float* Xs   = W1s + 64 * W1STR;         // 8704
    float* Gs   = Xs + 128 * XSTR;          // 8704
    float* tS   = Gs + 128 * GSTR;          // 64*228 = 14592
    float* shS0 = tS + 64 * TSTR;           // 1280
    float* shS1 = shS0 + 128 * 10;          // 1280
    int*   dstS0 = (int*)(shS1 + 128 * 10); // 128
    int*   dstS1 = dstS0 + 128;             // 128
    float* b1s  = (float*)(dstS1 + 128);    // 64
    float* gms  = b1s + 64;                 // 64
    float* bts  = gms + 64;                 // 64
    float* cS   = bts + 64;                 // 256
    float* b0s  = cS + 256;                 // 128

    const int tid = threadIdx.x;
    const int l   = tid & 31;
    const int w   = tid >> 5;
    const int mg  = w & 3;       // stage-B m group
    const int ng  = w >> 2;      // stage-B n group

    // -------- one-time loads: M, W1, constants --------
    for (int i = tid; i < 64 * 64; i += THREADS) {
        int k = i >> 6, c4 = i & 63;
        cp_async16(&Ms[k * MSTR + c4 * 4], &g_M[k * 256 + c4 * 4]);
    }
    for (int i = tid; i < 64 * 16; i += THREADS) {
        int k = i >> 4, c4 = i & 15;
        cp_async16(&W1s[k * W1STR + c4 * 4], &g_W1[k * 64 + c4 * 4]);
    }
    if (tid < 64) { b1s[tid] = rad_b1[tid]; gms[tid] = rad_gamma[tid]; bts[tid] = rad_beta[tid]; }
    if (tid >= 64 && tid < 64 + 256) cS[tid - 64] = g_c[tid - 64];
    if (tid >= 320 && tid < 448) b0s[tid - 320] = proj_b0[tid - 320] * 0.25f;

    // -------- prefetch first tile --------
    auto prefetch = [&](int e0, float* shB, int* dstB) {
        for (int i = tid; i < 128 * 16; i += THREADS) {
            int e = i >> 4, c4 = i & 15;
            int ge = e0 + e;
            int gc = (ge < E) ? ge : (E - 1);
            cp_async16_zfill(&Xs[e * XSTR + c4 * 4],
                             edge_scalars + (size_t)gc * 64 + c4 * 4,
                             (ge < E) ? 16 : 0);
        }
        for (int i = tid; i < 128 * 9; i += THREADS) {
            int e = i / 9, m = i - 9 * e;
            int ge = e0 + e;
            int gc = (ge < E) ? ge : (E - 1);
            cp_async4_zfill(&shB[e * 10 + m], edge_attr + (size_t)gc * 9 + m,
                            (ge < E) ? 4 : 0);
        }
        if (tid < 32) {
            int off = tid * 4;
            int ge = e0 + off;
            int gc = (ge + 3 < E) ? ge : ((E >= 4) ? E - 4 : 0);
            int rem = E - ge;
            int sz = (rem >= 4) ? 16 : ((rem > 0) ? rem * 4 : 0);
            cp_async16_zfill(&dstB[off], edge_dst + gc, sz);
        }
    };

    int t0 = blockIdx.x;
    if (t0 < nTiles) prefetch(t0 * 128, shS0, dstS0);
    asm volatile("cp.async.commit_group;" ::: "memory");

    int p = 0;
    for (int t = t0; t < nTiles; t += gridDim.x) {
        const int e0 = t * 128;
        float* shP  = p ? shS1 : shS0;
        int*   dstP = p ? dstS1 : dstS0;

        asm volatile("cp.async.wait_group 0;" ::: "memory");
        __syncthreads();

        // -------- stage A: h[128x64] = X @ W1 (mma tf32) --------
        {
            const int mt = w >> 1;
            const int nq = w & 1;
            const int m0 = mt * 16;
            float d[4][4] = {};
            const int ar0 = (m0 + (l >> 2)) * XSTR + (l & 3);
            const int ar1 = ar0 + 8 * XSTR;
            const uint32_t* W1u = (const uint32_t*)W1s;

            #pragma unroll
            for (int k0 = 0; k0 < 64; k0 += 8) {
                uint32_t a[4];
                a[0] = f2tf32(Xs[ar0 + k0]);
                a[1] = f2tf32(Xs[ar1 + k0]);
                a[2] = f2tf32(Xs[ar0 + k0 + 4]);
                a[3] = f2tf32(Xs[ar1 + k0 + 4]);
                #pragma unroll
                for (int nt = 0; nt < 4; nt++) {
                    int n0 = (nq * 4 + nt) * 8;
                    uint32_t b0 = W1u[(k0 + (l & 3)) * W1STR + n0 + (l >> 2)];
                    uint32_t b1 = W1u[(k0 + (l & 3) + 4) * W1STR + n0 + (l >> 2)];
                    mma_tf32(d[nt], a, b0, b1);
                }
            }
            __syncthreads();   // Xs reads done (also orders h stores below vs LN)
            #pragma unroll
            for (int nt = 0; nt < 4; nt++) {
                int c  = (nq * 4 + nt) * 8 + (l & 3) * 2;
                int r0 = m0 + (l >> 2);
                *(float2*)&Gs[r0 * GSTR + c]       = make_float2(d[nt][0], d[nt][1]);
                *(float2*)&Gs[(r0 + 8) * GSTR + c] = make_float2(d[nt][2], d[nt][3]);
            }
        }

        // -------- prefetch next tile's X/sh/dst (Xs now dead) --------
        {
            int tn = t + gridDim.x;
            if (tn < nTiles) prefetch(tn * 128, p ? shS0 : shS1, p ? dstS0 : dstS1);
            asm volatile("cp.async.commit_group;" ::: "memory");
        }
        __syncthreads();   // all h stores visible before LN

        // -------- LN + silu + tf32 convert (in place on Gs) --------
        {
            const int row = tid >> 2;
            const int qd  = tid & 3;
            float* hp = &Gs[row * GSTR + qd * 16];
            float v[16];
            float ps = 0.f, pq = 0.f;
            #pragma unroll
            for (int j = 0; j < 4; j++) {
                float4 x = ((const float4*)hp)[j];
                float b0 = b1s[qd * 16 + j * 4 + 0], b1 = b1s[qd * 16 + j * 4 + 1];
                float b2 = b1s[qd * 16 + j * 4 + 2], b3 = b1s[qd * 16 + j * 4 + 3];
                v[j * 4 + 0] = x.x + b0; v[j * 4 + 1] = x.y + b1;
                v[j * 4 + 2] = x.z + b2; v[j * 4 + 3] = x.w + b3;
                #pragma unroll
                for (int u = 0; u < 4; u++) { ps += v[j * 4 + u]; pq += v[j * 4 + u] * v[j * 4 + u]; }
            }
            ps += __shfl_xor_sync(0xffffffffu, ps, 1);
            pq += __shfl_xor_sync(0xffffffffu, pq, 1);
            ps += __shfl_xor_sync(0xffffffffu, ps, 2);
            pq += __shfl_xor_sync(0xffffffffu, pq, 2);
            float mu   = ps * (1.f / 64.f);
            float var  = pq * (1.f / 64.f) - mu * mu;
            float rstd = rsqrtf(var + 1e-5f);
            uint32_t o[16];
            #pragma unroll
            for (int u = 0; u < 16; u++) {
                int jj = qd * 16 + u;
                float g = (v[u] - mu) * rstd * gms[jj] + bts[jj];
                g = __fdividef(g, 1.f + __expf(-g));   // silu
                o[u] = f2tf32(g);
            }
            #pragma unroll
            for (int j = 0; j < 4; j++)
                ((uint4*)hp)[j] = make_uint4(o[j * 4], o[j * 4 + 1], o[j * 4 + 2], o[j * 4 + 3]);
        }
        __syncthreads();

        // -------- stage B: t[128x224] = G @ M + c (mma tf32) --------
        float d[2][7][4] = {};
        {
            const int m0 = mg * 32;
            const int n0 = ng * 56;
            const uint32_t* Gu = (const uint32_t*)Gs;
            const uint32_t* Mu = (const uint32_t*)Ms;
            const int ar00 = (m0 + (l >> 2)) * GSTR + (l & 3);

            #pragma unroll
            for (int k0 = 0; k0 < 64; k0 += 8) {
                uint32_t a[2][4];
                #pragma unroll
                for (int mt = 0; mt < 2; mt++) {
                    int base = ar00 + mt * 16 * GSTR + k0;
                    a[mt][0] = Gu[base];
                    a[mt][1] = Gu[base + 8 * GSTR];
                    a[mt][2] = Gu[base + 4];
                    a[mt][3] = Gu[base + 8 * GSTR + 4];
                }
                const int brow = (k0 + (l & 3)) * MSTR + n0 + (l >> 2);
                #pragma unroll
                for (int jt = 0; jt < 7; jt++) {
                    uint32_t b0 = Mu[brow + jt * 8];
                    uint32_t b1 = Mu[brow + 4 * MSTR + jt * 8];
                    mma_tf32(d[0][jt], a[0], b0, b1);
                    mma_tf32(d[1][jt], a[1], b0, b1);
                }
            }
        }

        // -------- stage C: two halves of 64 edges --------
        #pragma unroll
        for (int half = 0; half < 2; half++) {
            __syncthreads();   // prev tS reads done / mma reads done
            if ((mg >> 1) == half) {
                const int m0 = mg * 32 - half * 64;   // 0 or 32
                const int n0 = ng * 56;
                #pragma unroll
                for (int jt = 0; jt < 7; jt++) {
                    int c = n0 + jt * 8 + (l & 3) * 2;
                    float c0 = cS[c], c1 = cS[c + 1];
                    #pragma unroll
                    for (int mt = 0; mt < 2; mt++) {
                        int r0 = m0 + mt * 16 + (l >> 2);
                        *(float2*)&tS[r0 * TSTR + c] =
                            make_float2(d[mt][jt][0] + c0, d[mt][jt][1] + c1);
                        *(float2*)&tS[(r0 + 8) * TSTR + c] =
                            make_float2(d[mt][jt][2] + c0, d[mt][jt][3] + c1);
                    }
                }
            }
            __syncthreads();

            // balanced scatter: 16 warps x 4 edges
            const float4 b0v = *(const float4*)&b0s[l * 4];
            #pragma unroll 1
            for (int i = 0; i < 4; i++) {
                const int er = w * 4 + i;             // row in tS
                const int e  = half * 64 + er;        // edge in tile
                if (e0 + e >= E) continue;
                const float* te = &tS[er * TSTR];
                const float* sh = &shP[e * 10];
                float* base = out + (size_t)dstP[e] * 480;
                const float s0 = sh[0];

                {
                    float4 v = *(const float4*)&te[l * 4];
                    red4(base + l * 4,
                         fmaf(s0, v.x, b0v.x), fmaf(s0, v.y, b0v.y),
                         fmaf(s0, v.z, b0v.z), fmaf(s0, v.w, b0v.w));
                }
                #pragma unroll
                for (int r = 0; r < 2; r++) {
                    int j = l + r * 32;
                    if (j < 48) {
                        int pidx = 4 * j;
                        int q = (pidx * 0x5556) >> 16;
                        int m = pidx - 3 * q;
                        float ta = te[128 + q];
                        float tb = te[128 + q + 1];
                        float v[4];
                        #pragma unroll
                        for (int ii = 0; ii < 4; ii++) {
                            int mi = m + ii;
                            int f  = (mi >= 3);
                            float sv = sh[1 + mi - 3 * f];
                            v[ii] = (f ? tb : ta) * sv;
                        }
                        red4(base + 128 + pidx, v[0], v[1], v[2], v[3]);
                    }
                }
                #pragma unroll
                for (int r = 0; r < 2; r++) {
                    int j = l + r * 32;
                    if (j < 40) {
                        int pidx = 4 * j;
                        int q = (pidx * 0x3334) >> 16;
                        int m = pidx - 5 * q;
                        int qb = (q + 1 > 31) ? 31 : q + 1;
                        float ta = te[192 + q];
                        float tb = te[192 + qb];
                        float v[4];
                        #pragma unroll
                        for (int ii = 0; ii < 4; ii++) {
                            int mi = m + ii;
                            int f  = (mi >= 5);
                            float sv = sh[4 + mi - 5 * f];
                            v[ii] = (f ? tb : ta) * sv;
                        }
                        red4(base + 320 + pidx, v[0], v[1], v[2], v[3]);
                    }
                }
            }
        }
        p ^= 1;
    }
}

// ---------------------------------------------------------------------------
extern "C" void kernel_launch(void* const* d_in, const int* in_sizes, int n_in,
                              void* d_out, int out_size) {
    const float* edge_attr    = (const float*)d_in[1];
    const float* edge_scalars = (const float*)d_in[2];
    const int*   edge_dst     = (const int*)d_in[4];
    const float* exp_w   = (const float*)d_in[6];
    const float* exp_b   = (const float*)d_in[7];
    const float* rad_w1  = (const float*)d_in[8];
    const float* rad_b1  = (const float*)d_in[9];
    const float* rad_gamma = (const float*)d_in[10];
    const float* rad_beta  = (const float*)d_in[11];
    const float* rad_w2  = (const float*)d_in[12];
    const float* rad_b2  = (const float*)d_in[13];
    const float* proj_w0 = (const float*)d_in[14];
    const float* proj_b0 = (const float*)d_in[15];
    const float* proj_w1 = (const float*)d_in[16];
    const float* proj_w2 = (const float*)d_in[17];
    float* out = (float*)d_out;
    const int E = in_sizes[4];

    cudaMemsetAsync(d_out, 0, (size_t)out_size * sizeof(float));

    precompute_kernel<<<65, 256>>>(exp_w, exp_b, rad_w2, rad_b2,
                                   proj_w0, proj_w1, proj_w2);
    w1_prep_kernel<<<16, 256>>>(rad_w1);

    const size_t SMEM_FLOATS =
        64 * MSTR + 64 * W1STR + 128 * XSTR + 128 * GSTR + 64 * TSTR +
        2 * 128 * 10 + 2 * 128 + 64 * 3 + 256 + 128;
    const size_t SMEM_BYTES = SMEM_FLOATS * sizeof(float);
    cudaFuncSetAttribute(edge_main_kernel,
                         cudaFuncAttributeMaxDynamicSharedMemorySize, (int)SMEM_BYTES);

    int sms = 148;
    cudaDeviceGetAttribute(&sms, cudaDevAttrMultiProcessorCount, 0);
    const int nTiles = (E + 127) / 128;
    const int grid = (nTiles < sms) ? nTiles : sms;

    edge_main_kernel<<<grid, THREADS, SMEM_BYTES>>>(
        edge_attr, edge_scalars, edge_dst,
        rad_b1, rad_gamma, rad_beta,
        proj_b0, out, E, nTiles);
}

// round 6
// speedup vs baseline: 2.6891x; 1.0782x over previous
#include <cuda_runtime.h>
#include <cuda_bf16.h>
#include <cstdint>

#define THREADS 512
#define RCOLS   224
#define MSTR    264     // Ms smem row stride (mod 32 == 8 -> conflict-free B frags)
#define XSTR    68      // Xs row stride (mod 32 == 4 -> conflict-free A frags)
#define GSTR    68
#define W1STR   72      // W1 row stride (mod 32 == 8)
#define TSTR    228     // t staging row stride (64 rows per half)

// Precomputed fused weight M[64][256] (tf32 bits; includes diag(s), proj, 0.25),
// bias row c[256] (fp32), and tf32-rounded W1.
__device__ __align__(16) float g_M[64 * 256];
__device__ __align__(16) float g_c[256];
__device__ __align__(16) float g_W1[64 * 64];

__device__ __forceinline__ uint32_t f2tf32(float f) {
    uint32_t u;
    asm("cvt.rna.tf32.f32 %0, %1;" : "=r"(u) : "f"(f));
    return u;
}

// ---------------------------------------------------------------------------
// Precompute, latency-optimized: c-loop split 4-way across threads, smem reduce.
// Blocks 0..64: M rows (64 = bias row). Blocks 65..68: W1 tf32 conversion.
// ---------------------------------------------------------------------------
__global__ __launch_bounds__(1024)
void precompute_kernel(const float* __restrict__ exp_w,
                       const float* __restrict__ exp_b,
                       const float* __restrict__ rad_w2,
                       const float* __restrict__ rad_b2,
                       const float* __restrict__ pw0,
                       const float* __restrict__ pw1,
                       const float* __restrict__ pw2,
                       const float* __restrict__ rad_w1) {
    int k = blockIdx.x;
    int tid = threadIdx.x;

    if (k >= 65) {                       // W1 conversion: 4 blocks x 1024
        int i = (k - 65) * 1024 + tid;
        if (i < 64 * 64) g_W1[i] = __uint_as_float(f2tf32(rad_w1[i]));
        return;
    }

    __shared__ float s_s[128];
    __shared__ float s_w[384];
    __shared__ float part[4][256];

    if (tid < 128) s_s[tid] = exp_w[tid] + exp_b[tid];
    if (tid >= 128 && tid < 512) {
        int i = tid - 128;
        s_w[i] = (k < 64) ? rad_w2[k * 384 + i] : rad_b2[i];
    }
    __syncthreads();

    const int cs  = tid >> 8;    // 0..3: c chunk
    const int col = tid & 255;   // 0..255
    float acc = 0.f;
    if (col < RCOLS) {
        const float* P;
        int d, woff, pstride;
        if (col < 128)      { P = pw0; d = col;       woff = 0;   pstride = 128; }
        else if (col < 192) { P = pw1; d = col - 128; woff = 128; pstride = 64;  }
        else                { P = pw2; d = col - 192; woff = 256; pstride = 32;  }
        const int c0 = cs * 32;
        #pragma unroll 8
        for (int c = c0; c < c0 + 32; c++)
            acc += s_w[woff + c] * s_s[c] * __ldg(&P[c * pstride + d]);
    }
    part[cs][col] = acc;
    __syncthreads();

    if (tid < 256) {
        float sum = (part[0][tid] + part[1][tid]) + (part[2][tid] + part[3][tid]);
        sum *= 0.25f;   // 1/sqrt(AVG_AGG)
        if (k < 64) g_M[k * 256 + tid] = __uint_as_float(f2tf32(sum));
        else        g_c[tid] = sum;
    }
}

// ---------------------------------------------------------------------------
__device__ __forceinline__ void red4(float* p, float a, float b, float c, float d) {
    asm volatile("red.global.add.v4.f32 [%0], {%1, %2, %3, %4};"
                 :: "l"(p), "f"(a), "f"(b), "f"(c), "f"(d) : "memory");
}

__device__ __forceinline__ void cp_async16(void* smem_ptr, const void* gmem) {
    uint32_t s = (uint32_t)__cvta_generic_to_shared(smem_ptr);
    asm volatile("cp.async.cg.shared.global [%0], [%1], 16;" :: "r"(s), "l"(gmem));
}
__device__ __forceinline__ void cp_async16_zfill(void* smem_ptr, const void* gmem, int srcsz) {
    uint32_t s = (uint32_t)__cvta_generic_to_shared(smem_ptr);
    asm volatile("cp.async.cg.shared.global [%0], [%1], 16, %2;"
                 :: "r"(s), "l"(gmem), "r"(srcsz));
}
__device__ __forceinline__ void cp_async4_zfill(void* smem_ptr, const void* gmem, int srcsz) {
    uint32_t s = (uint32_t)__cvta_generic_to_shared(smem_ptr);
    asm volatile("cp.async.ca.shared.global [%0], [%1], 4, %2;"
                 :: "r"(s), "l"(gmem), "r"(srcsz));
}

__device__ __forceinline__ void mma_tf32(float d[4], const uint32_t a[4],
                                         uint32_t b0, uint32_t b1) {
    asm volatile(
        "mma.sync.aligned.m16n8k8.row.col.f32.tf32.tf32.f32 "
        "{%0,%1,%2,%3}, {%4,%5,%6,%7}, {%8,%9}, {%0,%1,%2,%3};"
        : "+f"(d[0]), "+f"(d[1]), "+f"(d[2]), "+f"(d[3])
        : "r"(a[0]), "r"(a[1]), "r"(a[2]), "r"(a[3]), "r"(b0), "r"(b1));
}

// ---------------------------------------------------------------------------
// Persistent kernel: each CTA loops over 128-edge tiles (stride gridDim).
// M/W1 loaded once; next-tile X/sh/dst prefetched behind LN+stageB+scatter.
// ---------------------------------------------------------------------------
__global__ __launch_bounds__(THREADS, 1)
void edge_main_kernel(const float* __restrict__ edge_attr,
                      const float* __restrict__ edge_scalars,
                      const int*   __restrict__ edge_dst,
                      const float* __restrict__ rad_b1,
                      const float* __restrict__ rad_gamma,
                      const float* __restrict__ rad_beta,
                      const float* __restrict__ proj_b0,
                      float* __restrict__ out,
                      int E, int nTiles)
{
    extern __shared__ float smem[];
    float* Ms   = smem;                     // 16896
    float* W1s  = Ms + 64 * MSTR;           // 4608
    float* Xs   = W1s + 64 * W1STR;         // 8704
    float* Gs   = Xs + 128 * XSTR;          // 8704
    float* tS   = Gs + 128 * GSTR;          // 64*228 = 14592
    float* shS0 = tS + 64 * TSTR;           // 1280
    float* shS1 = shS0 + 128 * 10;          // 1280
    int*   dstS0 = (int*)(shS1 + 128 * 10); // 128
    int*   dstS1 = dstS0 + 128;             // 128
    float* b1s  = (float*)(dstS1 + 128);    // 64
    float* gms  = b1s + 64;                 // 64
    float* bts  = gms + 64;                 // 64
    float* cS   = bts + 64;                 // 256
    float* b0s  = cS + 256;                 // 128

    const int tid = threadIdx.x;
    const int l   = tid & 31;
    const int w   = tid >> 5;
    const int mg  = w & 3;       // stage-B m group
    const int ng  = w >> 2;      // stage-B n group

    // -------- one-time loads: M, W1, constants --------
    for (int i = tid; i < 64 * 64; i += THREADS) {
        int k = i >> 6, c4 = i & 63;
        cp_async16(&Ms[k * MSTR + c4 * 4], &g_M[k * 256 + c4 * 4]);
    }
    for (int i = tid; i < 64 * 16; i += THREADS) {
        int k = i >> 4, c4 = i & 15;
        cp_async16(&W1s[k * W1STR + c4 * 4], &g_W1[k * 64 + c4 * 4]);
    }
    if (tid < 64) { b1s[tid] = rad_b1[tid]; gms[tid] = rad_gamma[tid]; bts[tid] = rad_beta[tid]; }
    if (tid >= 64 && tid < 64 + 256) cS[tid - 64] = g_c[tid - 64];
    if (tid >= 320 && tid < 448) b0s[tid - 320] = proj_b0[tid - 320] * 0.25f;

    // -------- tile prefetch helper --------
    auto prefetch = [&](int e0, float* shB, int* dstB) {
        for (int i = tid; i < 128 * 16; i += THREADS) {
            int e = i >> 4, c4 = i & 15;
            int ge = e0 + e;
            int gc = (ge < E) ? ge : (E - 1);
            cp_async16_zfill(&Xs[e * XSTR + c4 * 4],
                             edge_scalars + (size_t)gc * 64 + c4 * 4,
                             (ge < E) ? 16 : 0);
        }
        for (int i = tid; i < 128 * 9; i += THREADS) {
            int e = i / 9, m = i - 9 * e;
            int ge = e0 + e;
            int gc = (ge < E) ? ge : (E - 1);
            cp_async4_zfill(&shB[e * 10 + m], edge_attr + (size_t)gc * 9 + m,
                            (ge < E) ? 4 : 0);
        }
        if (tid < 32) {
            int off = tid * 4;
            int ge = e0 + off;
            int gc = (ge + 3 < E) ? ge : ((E >= 4) ? E - 4 : 0);
            int rem = E - ge;
            int sz = (rem >= 4) ? 16 : ((rem > 0) ? rem * 4 : 0);
            cp_async16_zfill(&dstB[off], edge_dst + gc, sz);
        }
    };

    int t0 = blockIdx.x;
    if (t0 < nTiles) prefetch(t0 * 128, shS0, dstS0);
    asm volatile("cp.async.commit_group;" ::: "memory");

    int p = 0;
    for (int t = t0; t < nTiles; t += gridDim.x) {
        const int e0 = t * 128;
        float* shP  = p ? shS1 : shS0;
        int*   dstP = p ? dstS1 : dstS0;

        asm volatile("cp.async.wait_group 0;" ::: "memory");
        __syncthreads();

        // -------- stage A: h[128x64] = X @ W1 (mma tf32) --------
        {
            const int mt = w >> 1;
            const int nq = w & 1;
            const int m0 = mt * 16;
            float d[4][4] = {};
            const int ar0 = (m0 + (l >> 2)) * XSTR + (l & 3);
            const int ar1 = ar0 + 8 * XSTR;
            const uint32_t* W1u = (const uint32_t*)W1s;

            #pragma unroll
            for (int k0 = 0; k0 < 64; k0 += 8) {
                uint32_t a[4];
                a[0] = f2tf32(Xs[ar0 + k0]);
                a[1] = f2tf32(Xs[ar1 + k0]);
                a[2] = f2tf32(Xs[ar0 + k0 + 4]);
                a[3] = f2tf32(Xs[ar1 + k0 + 4]);
                #pragma unroll
                for (int nt = 0; nt < 4; nt++) {
                    int n0 = (nq * 4 + nt) * 8;
                    uint32_t b0 = W1u[(k0 + (l & 3)) * W1STR + n0 + (l >> 2)];
                    uint32_t b1 = W1u[(k0 + (l & 3) + 4) * W1STR + n0 + (l >> 2)];
                    mma_tf32(d[nt], a, b0, b1);
                }
            }
            // store raw h into Gs (private buffer, no hazard before the barrier)
            #pragma unroll
            for (int nt = 0; nt < 4; nt++) {
                int c  = (nq * 4 + nt) * 8 + (l & 3) * 2;
                int r0 = m0 + (l >> 2);
                *(float2*)&Gs[r0 * GSTR + c]       = make_float2(d[nt][0], d[nt][1]);
                *(float2*)&Gs[(r0 + 8) * GSTR + c] = make_float2(d[nt][2], d[nt][3]);
            }
        }
        __syncthreads();   // Xs reads done AND h stores visible (merged barrier)

        // -------- prefetch next tile's X/sh/dst (Xs now dead) --------
        {
            int tn = t + gridDim.x;
            if (tn < nTiles) prefetch(tn * 128, p ? shS0 : shS1, p ? dstS0 : dstS1);
            asm volatile("cp.async.commit_group;" ::: "memory");
        }

        // -------- LN + silu + tf32 convert (in place on Gs) --------
        {
            const int row = tid >> 2;
            const int qd  = tid & 3;
            float* hp = &Gs[row * GSTR + qd * 16];
            float v[16];
            float ps = 0.f, pq = 0.f;
            #pragma unroll
            for (int j = 0; j < 4; j++) {
                float4 x = ((const float4*)hp)[j];
                float b0 = b1s[qd * 16 + j * 4 + 0], b1 = b1s[qd * 16 + j * 4 + 1];
                float b2 = b1s[qd * 16 + j * 4 + 2], b3 = b1s[qd * 16 + j * 4 + 3];
                v[j * 4 + 0] = x.x + b0; v[j * 4 + 1] = x.y + b1;
                v[j * 4 + 2] = x.z + b2; v[j * 4 + 3] = x.w + b3;
                #pragma unroll
                for (int u = 0; u < 4; u++) { ps += v[j * 4 + u]; pq += v[j * 4 + u] * v[j * 4 + u]; }
            }
            ps += __shfl_xor_sync(0xffffffffu, ps, 1);
            pq += __shfl_xor_sync(0xffffffffu, pq, 1);
            ps += __shfl_xor_sync(0xffffffffu, ps, 2);
            pq += __shfl_xor_sync(0xffffffffu, pq, 2);
            float mu   = ps * (1.f / 64.f);
            float var  = pq * (1.f / 64.f) - mu * mu;
            float rstd = rsqrtf(var + 1e-5f);
            uint32_t o[16];
            #pragma unroll
            for (int u = 0; u < 16; u++) {
                int jj = qd * 16 + u;
                float g = (v[u] - mu) * rstd * gms[jj] + bts[jj];
                g = __fdividef(g, 1.f + __expf(-g));   // silu
                o[u] = f2tf32(g);
            }
            #pragma unroll
            for (int j = 0; j < 4; j++)
                ((uint4*)hp)[j] = make_uint4(o[j * 4], o[j * 4 + 1], o[j * 4 + 2], o[j * 4 + 3]);
        }
        __syncthreads();

        // -------- stage B: t[128x224] = G @ M + c (mma tf32) --------
        float d[2][7][4] = {};
        {
            const int m0 = mg * 32;
            const int n0 = ng * 56;
            const uint32_t* Gu = (const uint32_t*)Gs;
            const uint32_t* Mu = (const uint32_t*)Ms;
            const int ar00 = (m0 + (l >> 2)) * GSTR + (l & 3);

            #pragma unroll
            for (int k0 = 0; k0 < 64; k0 += 8) {
                uint32_t a[2][4];
                #pragma unroll
                for (int mt = 0; mt < 2; mt++) {
                    int base = ar00 + mt * 16 * GSTR + k0;
                    a[mt][0] = Gu[base];
                    a[mt][1] = Gu[base + 8 * GSTR];
                    a[mt][2] = Gu[base + 4];
                    a[mt][3] = Gu[base + 8 * GSTR + 4];
                }
                const int brow = (k0 + (l & 3)) * MSTR + n0 + (l >> 2);
                #pragma unroll
                for (int jt = 0; jt < 7; jt++) {
                    uint32_t b0 = Mu[brow + jt * 8];
                    uint32_t b1 = Mu[brow + 4 * MSTR + jt * 8];
                    mma_tf32(d[0][jt], a[0], b0, b1);
                    mma_tf32(d[1][jt], a[1], b0, b1);
                }
            }
        }

        // -------- stage C: two halves of 64 edges --------
        #pragma unroll
        for (int half = 0; half < 2; half++) {
            __syncthreads();   // prev tS reads done
            if ((mg >> 1) == half) {
                const int m0 = mg * 32 - half * 64;   // 0 or 32
                const int n0 = ng * 56;
                #pragma unroll
                for (int jt = 0; jt < 7; jt++) {
                    int c = n0 + jt * 8 + (l & 3) * 2;
                    float c0 = cS[c], c1 = cS[c + 1];
                    #pragma unroll
                    for (int mt = 0; mt < 2; mt++) {
                        int r0 = m0 + mt * 16 + (l >> 2);
                        *(float2*)&tS[r0 * TSTR + c] =
                            make_float2(d[mt][jt][0] + c0, d[mt][jt][1] + c1);
                        *(float2*)&tS[(r0 + 8) * TSTR + c] =
                            make_float2(d[mt][jt][2] + c0, d[mt][jt][3] + c1);
                    }
                }
            }
            __syncthreads();

            // balanced scatter: 16 warps x 4 edges
            const float4 b0v = *(const float4*)&b0s[l * 4];
            #pragma unroll 1
            for (int i = 0; i < 4; i++) {
                const int er = w * 4 + i;             // row in tS
                const int e  = half * 64 + er;        // edge in tile
                if (e0 + e >= E) continue;
                const float* te = &tS[er * TSTR];
                const float* sh = &shP[e * 10];
                float* base = out + (size_t)dstP[e] * 480;
                const float s0 = sh[0];

                {
                    float4 v = *(const float4*)&te[l * 4];
                    red4(base + l * 4,
                         fmaf(s0, v.x, b0v.x), fmaf(s0, v.y, b0v.y),
                         fmaf(s0, v.z, b0v.z), fmaf(s0, v.w, b0v.w));
                }
                #pragma unroll
                for (int r = 0; r < 2; r++) {
                    int j = l + r * 32;
                    if (j < 48) {
                        int pidx = 4 * j;
                        int q = (pidx * 0x5556) >> 16;
                        int m = pidx - 3 * q;
                        float ta = te[128 + q];
                        float tb = te[128 + q + 1];
                        float v[4];
                        #pragma unroll
                        for (int ii = 0; ii < 4; ii++) {
                            int mi = m + ii;
                            int f  = (mi >= 3);
                            float sv = sh[1 + mi - 3 * f];
                            v[ii] = (f ? tb : ta) * sv;
                        }
                        red4(base + 128 + pidx, v[0], v[1], v[2], v[3]);
                    }
                }
                #pragma unroll
                for (int r = 0; r < 2; r++) {
                    int j = l + r * 32;
                    if (j < 40) {
                        int pidx = 4 * j;
                        int q = (pidx * 0x3334) >> 16;
                        int m = pidx - 5 * q;
                        int qb = (q + 1 > 31) ? 31 : q + 1;
                        float ta = te[192 + q];
                        float tb = te[192 + qb];
                        float v[4];
                        #pragma unroll
                        for (int ii = 0; ii < 4; ii++) {
                            int mi = m + ii;
                            int f  = (mi >= 5);
                            float sv = sh[4 + mi - 5 * f];
                            v[ii] = (f ? tb : ta) * sv;
                        }
                        red4(base + 320 + pidx, v[0], v[1], v[2], v[3]);
                    }
                }
            }
        }
        p ^= 1;
    }
}

// ---------------------------------------------------------------------------
extern "C" void kernel_launch(void* const* d_in, const int* in_sizes, int n_in,
                              void* d_out, int out_size) {
    const float* edge_attr    = (const float*)d_in[1];
    const float* edge_scalars = (const float*)d_in[2];
    const int*   edge_dst     = (const int*)d_in[4];
    const float* exp_w   = (const float*)d_in[6];
    const float* exp_b   = (const float*)d_in[7];
    const float* rad_w1  = (const float*)d_in[8];
    const float* rad_b1  = (const float*)d_in[9];
    const float* rad_gamma = (const float*)d_in[10];
    const float* rad_beta  = (const float*)d_in[11];
    const float* rad_w2  = (const float*)d_in[12];
    const float* rad_b2  = (const float*)d_in[13];
    const float* proj_w0 = (const float*)d_in[14];
    const float* proj_b0 = (const float*)d_in[15];
    const float* proj_w1 = (const float*)d_in[16];
    const float* proj_w2 = (const float*)d_in[17];
    float* out = (float*)d_out;
    const int E = in_sizes[4];

    cudaMemsetAsync(d_out, 0, (size_t)out_size * sizeof(float));

    precompute_kernel<<<69, 1024>>>(exp_w, exp_b, rad_w2, rad_b2,
                                    proj_w0, proj_w1, proj_w2, rad_w1);

    const size_t SMEM_FLOATS =
        64 * MSTR + 64 * W1STR + 128 * XSTR + 128 * GSTR + 64 * TSTR +
        2 * 128 * 10 + 2 * 128 + 64 * 3 + 256 + 128;
    const size_t SMEM_BYTES = SMEM_FLOATS * sizeof(float);
    cudaFuncSetAttribute(edge_main_kernel,
                         cudaFuncAttributeMaxDynamicSharedMemorySize, (int)SMEM_BYTES);

    int sms = 148;
    cudaDeviceGetAttribute(&sms, cudaDevAttrMultiProcessorCount, 0);
    const int nTiles = (E + 127) / 128;
    const int grid = (nTiles < sms) ? nTiles : sms;

    edge_main_kernel<<<grid, THREADS, SMEM_BYTES>>>(
        edge_attr, edge_scalars, edge_dst,
        rad_b1, rad_gamma, rad_beta,
        proj_b0, out, E, nTiles);
}